// round 2
// baseline (speedup 1.0000x reference)
#include <cuda_runtime.h>
#include <math.h>

#define B_ROWS 16384
#define IN_DIM 1024
#define OUT_DIM 1024
#define N_EXP 8

// ---------------- static device scratch (no allocations allowed) ----------------
__device__ float g_combined[(size_t)B_ROWS * IN_DIM];   // 64 MB
__device__ float g_H[(size_t)B_ROWS * OUT_DIM];         // 64 MB (gelu(x@w1+b1) per expert)
__device__ float g_Y[(size_t)B_ROWS * OUT_DIM];         // 64 MB (h@w2+b2 per expert)
__device__ float g_wts[(size_t)B_ROWS * N_EXP];         // 512 KB (softmax router weights)

// ---------------- concat: combined = [z_s | z_e] ----------------
__global__ void concat_kernel(const float* __restrict__ zs,
                              const float* __restrict__ ze)
{
    size_t gid = (size_t)blockIdx.x * blockDim.x + threadIdx.x;
    size_t total = (size_t)B_ROWS * IN_DIM;
    if (gid >= total) return;
    size_t b = gid >> 10;        // /1024
    int    i = (int)(gid & 1023);
    g_combined[gid] = (i < 512) ? zs[b * 512 + i] : ze[b * 512 + (i - 512)];
}

// ---------------- router: softmax(combined @ rw + rb) ----------------
__global__ void router_kernel(const float* __restrict__ rw,
                              const float* __restrict__ rb)
{
    __shared__ float red[N_EXP][256];
    const int b = blockIdx.x;
    const int tid = threadIdx.x;
    const float* x = g_combined + (size_t)b * IN_DIM;

    float acc[N_EXP];
#pragma unroll
    for (int e = 0; e < N_EXP; e++) acc[e] = 0.f;

    for (int i = tid; i < IN_DIM; i += 256) {
        float xv = x[i];
        const float* w = rw + (size_t)i * N_EXP;
#pragma unroll
        for (int e = 0; e < N_EXP; e++) acc[e] += xv * w[e];
    }
#pragma unroll
    for (int e = 0; e < N_EXP; e++) red[e][tid] = acc[e];
    __syncthreads();

    for (int st = 128; st > 0; st >>= 1) {
        if (tid < st) {
#pragma unroll
            for (int e = 0; e < N_EXP; e++) red[e][tid] += red[e][tid + st];
        }
        __syncthreads();
    }

    if (tid == 0) {
        float lg[N_EXP];
        float mx = -1e30f;
#pragma unroll
        for (int e = 0; e < N_EXP; e++) {
            lg[e] = red[e][0] + rb[e];
            mx = fmaxf(mx, lg[e]);
        }
        float sum = 0.f;
#pragma unroll
        for (int e = 0; e < N_EXP; e++) { lg[e] = expf(lg[e] - mx); sum += lg[e]; }
        float inv = 1.f / sum;
#pragma unroll
        for (int e = 0; e < N_EXP; e++) g_wts[(size_t)b * N_EXP + e] = lg[e] * inv;
    }
}

// ---------------- tiled fp32 SGEMM: C = act(A @ B + bias) ----------------
// A: MxK row-major, B: KxN row-major, all dims multiples of tile sizes.
#define BM 128
#define BN 128
#define BK 8
#define TM 8
#define TN 8

__global__ __launch_bounds__(256) void sgemm_kernel(
    const float* __restrict__ A, const float* __restrict__ Bm,
    const float* __restrict__ bias, float* __restrict__ C,
    int M, int N, int K, int apply_gelu)
{
    __shared__ float As[BK][BM];
    __shared__ float Bs[BK][BN];

    const int tid = threadIdx.x;
    const size_t brow = blockIdx.y, bcol = blockIdx.x;

    A  += brow * BM * (size_t)K;
    Bm += bcol * BN;
    C  += brow * BM * (size_t)N + bcol * BN;
    bias += bcol * BN;

    const int tr = tid >> 4;         // 0..15, row of 8x8 thread tile
    const int tc = tid & 15;         // 0..15, col of 8x8 thread tile
    const int aRow = tid >> 1;       // 0..127
    const int aCol = (tid & 1) * 4;  // 0 or 4
    const int bRow = tid >> 5;       // 0..7
    const int bCol = (tid & 31) * 4; // 0..124

    float acc[TM][TN];
#pragma unroll
    for (int i = 0; i < TM; i++)
#pragma unroll
        for (int j = 0; j < TN; j++) acc[i][j] = 0.f;

    for (int k0 = 0; k0 < K; k0 += BK) {
        float4 a4 = *(const float4*)(A + (size_t)aRow * K + k0 + aCol);
        As[aCol + 0][aRow] = a4.x;
        As[aCol + 1][aRow] = a4.y;
        As[aCol + 2][aRow] = a4.z;
        As[aCol + 3][aRow] = a4.w;
        *(float4*)(&Bs[bRow][bCol]) =
            *(const float4*)(Bm + (size_t)(k0 + bRow) * N + bCol);
        __syncthreads();

#pragma unroll
        for (int k = 0; k < BK; k++) {
            float ra[TM], rb[TN];
#pragma unroll
            for (int i = 0; i < TM; i++) ra[i] = As[k][tr * TM + i];
#pragma unroll
            for (int j = 0; j < TN; j++) rb[j] = Bs[k][tc * TN + j];
#pragma unroll
            for (int i = 0; i < TM; i++)
#pragma unroll
                for (int j = 0; j < TN; j++)
                    acc[i][j] = fmaf(ra[i], rb[j], acc[i][j]);
        }
        __syncthreads();
    }

#pragma unroll
    for (int i = 0; i < TM; i++) {
        int row = tr * TM + i;
#pragma unroll
        for (int j = 0; j < TN; j++) {
            int col = tc * TN + j;
            float v = acc[i][j] + bias[col];
            if (apply_gelu)
                v = 0.5f * v * (1.0f + erff(v * 0.70710678118654752f)); // exact gelu
            C[(size_t)row * N + col] = v;
        }
    }
}

// ---------------- LayerNorm + weighted accumulate into out ----------------
__global__ void ln_acc_kernel(const float* __restrict__ gamma,
                              const float* __restrict__ beta,
                              float* __restrict__ out,
                              int e, int accumulate)
{
    __shared__ float row[OUT_DIM];
    __shared__ float red[256];
    const int b = blockIdx.x;
    const int tid = threadIdx.x;
    const float* y = g_Y + (size_t)b * OUT_DIM;

    float s = 0.f;
#pragma unroll
    for (int i = 0; i < 4; i++) {
        float v = y[tid + 256 * i];
        row[tid + 256 * i] = v;
        s += v;
    }
    red[tid] = s;
    __syncthreads();
    for (int st = 128; st > 0; st >>= 1) {
        if (tid < st) red[tid] += red[tid + st];
        __syncthreads();
    }
    float mu = red[0] * (1.f / OUT_DIM);
    __syncthreads();

    float s2 = 0.f;
#pragma unroll
    for (int i = 0; i < 4; i++) {
        float d = row[tid + 256 * i] - mu;
        s2 += d * d;
    }
    red[tid] = s2;
    __syncthreads();
    for (int st = 128; st > 0; st >>= 1) {
        if (tid < st) red[tid] += red[tid + st];
        __syncthreads();
    }
    float inv = rsqrtf(red[0] * (1.f / OUT_DIM) + 1e-5f);
    float w = g_wts[(size_t)b * N_EXP + e];

#pragma unroll
    for (int i = 0; i < 4; i++) {
        int o = tid + 256 * i;
        float v = ((row[o] - mu) * inv * gamma[o] + beta[o]) * w;
        size_t idx = (size_t)b * OUT_DIM + o;
        if (accumulate) out[idx] += v;
        else            out[idx] = v;
    }
}

// ---------------- host launch ----------------
extern "C" void kernel_launch(void* const* d_in, const int* in_sizes, int n_in,
                              void* d_out, int out_size)
{
    const float* z_s   = (const float*)d_in[0];
    const float* z_e   = (const float*)d_in[1];
    const float* rw    = (const float*)d_in[2];
    const float* rb    = (const float*)d_in[3];
    const float* w1    = (const float*)d_in[4];
    const float* b1    = (const float*)d_in[5];
    const float* w2    = (const float*)d_in[6];
    const float* b2    = (const float*)d_in[7];
    const float* gamma = (const float*)d_in[8];
    const float* beta  = (const float*)d_in[9];
    float* out = (float*)d_out;

    float *comb, *H, *Y;
    cudaGetSymbolAddress((void**)&comb, g_combined);
    cudaGetSymbolAddress((void**)&H, g_H);
    cudaGetSymbolAddress((void**)&Y, g_Y);

    // concat
    {
        size_t total = (size_t)B_ROWS * IN_DIM;
        int threads = 256;
        int blocks = (int)((total + threads - 1) / threads);
        concat_kernel<<<blocks, threads>>>(z_s, z_e);
    }
    // router softmax weights
    router_kernel<<<B_ROWS, 256>>>(rw, rb);

    dim3 gemm_grid(OUT_DIM / BN, B_ROWS / BM);
    for (int e = 0; e < N_EXP; e++) {
        // H = gelu(combined @ w1[e] + b1[e])
        sgemm_kernel<<<gemm_grid, 256>>>(
            comb, w1 + (size_t)e * IN_DIM * OUT_DIM, b1 + (size_t)e * OUT_DIM,
            H, B_ROWS, OUT_DIM, IN_DIM, 1);
        // Y = H @ w2[e] + b2[e]
        sgemm_kernel<<<gemm_grid, 256>>>(
            H, w2 + (size_t)e * OUT_DIM * OUT_DIM, b2 + (size_t)e * OUT_DIM,
            Y, B_ROWS, OUT_DIM, OUT_DIM, 0);
        // out (+)= wts[:,e] * LN(Y)
        ln_acc_kernel<<<B_ROWS, 256>>>(
            gamma + (size_t)e * OUT_DIM, beta + (size_t)e * OUT_DIM,
            out, e, e > 0 ? 1 : 0);
    }
}

// round 5
// speedup vs baseline: 2.7528x; 2.7528x over previous
#include <cuda_runtime.h>
#include <cuda_bf16.h>
#include <math.h>
#include <stdint.h>

#define B_ROWS 16384
#define DIMK   1024
#define N_EXP  8

// ---------------------------------------------------------------------------
// Static device scratch (no allocations allowed)
// ---------------------------------------------------------------------------
__device__ __nv_bfloat16 g_comb_hi[(size_t)B_ROWS * DIMK];            // 32 MB
__device__ __nv_bfloat16 g_comb_lo[(size_t)B_ROWS * DIMK];            // 32 MB
__device__ __nv_bfloat16 g_w1t_hi[(size_t)N_EXP * DIMK * DIMK];       // 16 MB  [e][n][k]
__device__ __nv_bfloat16 g_w1t_lo[(size_t)N_EXP * DIMK * DIMK];
__device__ __nv_bfloat16 g_w2t_hi[(size_t)N_EXP * DIMK * DIMK];
__device__ __nv_bfloat16 g_w2t_lo[(size_t)N_EXP * DIMK * DIMK];
__device__ __nv_bfloat16 g_H_hi[(size_t)N_EXP * B_ROWS * DIMK];       // 256 MB [e][m][k]
__device__ __nv_bfloat16 g_H_lo[(size_t)N_EXP * B_ROWS * DIMK];       // 256 MB
__device__ float         g_Y[(size_t)N_EXP * B_ROWS * DIMK];          // 512 MB [e][m][n]
__device__ float         g_wts[(size_t)B_ROWS * N_EXP];

// ---------------------------------------------------------------------------
// helpers (all sm_80-level PTX; nothing needing the 'a' target)
// ---------------------------------------------------------------------------
__device__ __forceinline__ void cp16(uint32_t dst, const void* src) {
    asm volatile("cp.async.cg.shared.global [%0], [%1], 16;"
                 :: "r"(dst), "l"(__cvta_generic_to_global(src)) : "memory");
}
__device__ __forceinline__ void ldsm_x4(uint32_t* r, uint32_t addr) {
    asm volatile("ldmatrix.sync.aligned.m8n8.x4.shared.b16 {%0,%1,%2,%3}, [%4];"
                 : "=r"(r[0]), "=r"(r[1]), "=r"(r[2]), "=r"(r[3]) : "r"(addr));
}
__device__ __forceinline__ void mma_bf16(float* d, const uint32_t* a, const uint32_t* b) {
    asm volatile("mma.sync.aligned.m16n8k16.row.col.f32.bf16.bf16.f32 "
                 "{%0,%1,%2,%3}, {%4,%5,%6,%7}, {%8,%9}, {%0,%1,%2,%3};"
                 : "+f"(d[0]), "+f"(d[1]), "+f"(d[2]), "+f"(d[3])
                 : "r"(a[0]), "r"(a[1]), "r"(a[2]), "r"(a[3]), "r"(b[0]), "r"(b[1]));
}
// swizzled byte offset within a [128 rows x 32 bf16] tile (64B rows, 4x16B chunks)
__device__ __forceinline__ uint32_t swz(int r, int c) {
    return (uint32_t)(r * 64 + ((c ^ ((r >> 1) & 3)) << 4));
}

// ---------------------------------------------------------------------------
// Split / transpose kernels
// ---------------------------------------------------------------------------
__global__ void split_comb_kernel(const float* __restrict__ zs,
                                  const float* __restrict__ ze) {
    size_t g = (size_t)blockIdx.x * blockDim.x + threadIdx.x;
    if (g >= (size_t)B_ROWS * DIMK) return;
    size_t b = g >> 10; int i = (int)(g & 1023);
    float v = (i < 512) ? zs[(b << 9) + i] : ze[(b << 9) + i - 512];
    __nv_bfloat16 h = __float2bfloat16_rn(v);
    g_comb_hi[g] = h;
    g_comb_lo[g] = __float2bfloat16_rn(v - __bfloat162float(h));
}

// w: [e][k][n] fp32 -> out: [e][n][k] bf16 hi/lo
__global__ void split_wT_kernel(const float* __restrict__ w,
                                __nv_bfloat16* __restrict__ thi,
                                __nv_bfloat16* __restrict__ tlo) {
    size_t g = (size_t)blockIdx.x * blockDim.x + threadIdx.x;
    if (g >= (size_t)N_EXP * DIMK * DIMK) return;
    size_t e = g >> 20;
    int k = (int)((g >> 10) & 1023);
    int n = (int)(g & 1023);
    float v = w[g];
    size_t o = (e << 20) + ((size_t)n << 10) + k;
    __nv_bfloat16 h = __float2bfloat16_rn(v);
    thi[o] = h;
    tlo[o] = __float2bfloat16_rn(v - __bfloat162float(h));
}

// ---------------------------------------------------------------------------
// Router softmax
// ---------------------------------------------------------------------------
__global__ void router_kernel(const float* __restrict__ zs,
                              const float* __restrict__ ze,
                              const float* __restrict__ rw,
                              const float* __restrict__ rb) {
    __shared__ float red[N_EXP][256];
    const int b = blockIdx.x;
    const int tid = threadIdx.x;

    float acc[N_EXP];
#pragma unroll
    for (int e = 0; e < N_EXP; e++) acc[e] = 0.f;

    for (int i = tid; i < DIMK; i += 256) {
        float xv = (i < 512) ? zs[(size_t)b * 512 + i] : ze[(size_t)b * 512 + i - 512];
        const float* w = rw + (size_t)i * N_EXP;
#pragma unroll
        for (int e = 0; e < N_EXP; e++) acc[e] += xv * w[e];
    }
#pragma unroll
    for (int e = 0; e < N_EXP; e++) red[e][tid] = acc[e];
    __syncthreads();
    for (int st = 128; st > 0; st >>= 1) {
        if (tid < st) {
#pragma unroll
            for (int e = 0; e < N_EXP; e++) red[e][tid] += red[e][tid + st];
        }
        __syncthreads();
    }
    if (tid == 0) {
        float lg[N_EXP], mx = -1e30f;
#pragma unroll
        for (int e = 0; e < N_EXP; e++) { lg[e] = red[e][0] + rb[e]; mx = fmaxf(mx, lg[e]); }
        float sum = 0.f;
#pragma unroll
        for (int e = 0; e < N_EXP; e++) { lg[e] = expf(lg[e] - mx); sum += lg[e]; }
        float inv = 1.f / sum;
#pragma unroll
        for (int e = 0; e < N_EXP; e++) g_wts[(size_t)b * N_EXP + e] = lg[e] * inv;
    }
}

// ---------------------------------------------------------------------------
// bf16 mma.sync GEMM with 3-term split: D = A @ B^T (+bias, +gelu/split)
//   A: [m][k] bf16 hi/lo, row-major, K=1024, per-expert stride a_estride
//   B: [n][k] bf16 hi/lo, row-major, per-expert stride 1024*1024
//   CTA tile 128x128, BK=32, 3-stage cp.async pipeline, 8 warps (2x4),
//   warp tile 64x32.
//   mode 1: out = bf16split(gelu(D + bias))  -> Ohi/Olo
//   mode 0: out = fp32(D + bias)             -> Of
// ---------------------------------------------------------------------------
#define TILE_B   8192                 // 128 x 32 bf16
#define STAGE_B  (4 * TILE_B)         // Ah, Al, Bh, Bl
#define STAGES   3
#define SMEM_BYTES (STAGES * STAGE_B) // 96 KB
#define CHUNKS   (DIMK / 32)          // 32

__device__ __forceinline__ void load_chunk(uint32_t stage_base,
                                           const __nv_bfloat16* pAh,
                                           const __nv_bfloat16* pAl,
                                           const __nv_bfloat16* pBh,
                                           const __nv_bfloat16* pBl,
                                           int k0, int tid) {
#pragma unroll
    for (int i = 0; i < 2; i++) {
        int id = tid + i * 256;        // 0..511
        int r = id >> 2;               // 0..127
        int c = id & 3;                // 16B chunk
        uint32_t o = swz(r, c);
        const size_t s = (size_t)r * DIMK + k0 + c * 8;
        cp16(stage_base + o,              pAh + s);
        cp16(stage_base + TILE_B + o,     pAl + s);
        cp16(stage_base + 2 * TILE_B + o, pBh + s);
        cp16(stage_base + 3 * TILE_B + o, pBl + s);
    }
}

__global__ void __launch_bounds__(256, 1) gemm_mma_kernel(
    const __nv_bfloat16* __restrict__ Ahi, const __nv_bfloat16* __restrict__ Alo,
    size_t a_estride,
    const __nv_bfloat16* __restrict__ Bhi, const __nv_bfloat16* __restrict__ Blo,
    const float* __restrict__ bias, int mode,
    __nv_bfloat16* __restrict__ Ohi, __nv_bfloat16* __restrict__ Olo,
    float* __restrict__ Of)
{
    extern __shared__ char smem[];
    const int tid  = threadIdx.x;
    const int wid  = tid >> 5;
    const int lane = tid & 31;
    const int cb = blockIdx.x;     // N block
    const int rb = blockIdx.y;     // M block
    const int e  = blockIdx.z;
    const int wm = (wid >> 2) * 64;   // warp m offset (0 / 64)
    const int wn = (wid & 3) * 32;    // warp n offset (0/32/64/96)

    const uint32_t sbase = (uint32_t)__cvta_generic_to_shared(smem);

    const __nv_bfloat16* pAh = Ahi + (size_t)e * a_estride + (size_t)rb * 128 * DIMK;
    const __nv_bfloat16* pAl = Alo + (size_t)e * a_estride + (size_t)rb * 128 * DIMK;
    const __nv_bfloat16* pBh = Bhi + ((size_t)e * DIMK + (size_t)cb * 128) * DIMK;
    const __nv_bfloat16* pBl = Blo + ((size_t)e * DIMK + (size_t)cb * 128) * DIMK;

    float acc[4][4][4];
#pragma unroll
    for (int i = 0; i < 4; i++)
#pragma unroll
        for (int j = 0; j < 4; j++)
#pragma unroll
            for (int k = 0; k < 4; k++) acc[i][j][k] = 0.f;

    // prefetch stages 0..STAGES-2
#pragma unroll
    for (int s = 0; s < STAGES - 1; s++) {
        load_chunk(sbase + s * STAGE_B, pAh, pAl, pBh, pBl, s * 32, tid);
        asm volatile("cp.async.commit_group;" ::: "memory");
    }

    // precomputed lane-level ldmatrix row/col pieces
    const int jA = lane >> 3;
    const int rA_base = ((jA & 1) << 3) + (lane & 7);   // + wm + mf*16
    const int cA_base = jA >> 1;                        // + kc0
    const int jB = lane >> 3;
    const int rB_base = ((jB >> 1) << 3) + (lane & 7);  // + wn + q*16
    const int cB_base = jB & 1;                         // + kc0

    for (int c = 0; c < CHUNKS; c++) {
        int pf = c + STAGES - 1;
        if (pf < CHUNKS)
            load_chunk(sbase + (pf % STAGES) * STAGE_B, pAh, pAl, pBh, pBl, pf * 32, tid);
        asm volatile("cp.async.commit_group;" ::: "memory");
        asm volatile("cp.async.wait_group %0;" :: "n"(STAGES - 2) : "memory");
        __syncthreads();

        const uint32_t ah_b = sbase + (c % STAGES) * STAGE_B;
        const uint32_t al_b = ah_b + TILE_B;
        const uint32_t bh_b = ah_b + 2 * TILE_B;
        const uint32_t bl_b = ah_b + 3 * TILE_B;

#pragma unroll
        for (int ks = 0; ks < 2; ks++) {
            const int kc0 = ks * 2;
            uint32_t bh[4][2], bl[4][2];
#pragma unroll
            for (int q = 0; q < 2; q++) {
                int rB = wn + q * 16 + rB_base;
                int cB = kc0 + cB_base;
                uint32_t o = swz(rB, cB);
                uint32_t t[4];
                ldsm_x4(t, bh_b + o);
                bh[2 * q][0] = t[0]; bh[2 * q][1] = t[1];
                bh[2 * q + 1][0] = t[2]; bh[2 * q + 1][1] = t[3];
                ldsm_x4(t, bl_b + o);
                bl[2 * q][0] = t[0]; bl[2 * q][1] = t[1];
                bl[2 * q + 1][0] = t[2]; bl[2 * q + 1][1] = t[3];
            }
#pragma unroll
            for (int mf = 0; mf < 4; mf++) {
                int rA = wm + mf * 16 + rA_base;
                int cA = kc0 + cA_base;
                uint32_t o = swz(rA, cA);
                uint32_t ah[4], al[4];
                ldsm_x4(ah, ah_b + o);
                ldsm_x4(al, al_b + o);
#pragma unroll
                for (int nf = 0; nf < 4; nf++) {
                    mma_bf16(acc[mf][nf], ah, bh[nf]);
                    mma_bf16(acc[mf][nf], ah, bl[nf]);
                    mma_bf16(acc[mf][nf], al, bh[nf]);
                }
            }
        }
        __syncthreads();
    }

    // --------------------------- epilogue ---------------------------
    const float* bias_e = bias + (size_t)e * DIMK;
#pragma unroll
    for (int mf = 0; mf < 4; mf++) {
#pragma unroll
        for (int nf = 0; nf < 4; nf++) {
#pragma unroll
            for (int h = 0; h < 2; h++) {       // two row halves of the frag
                int row = rb * 128 + wm + mf * 16 + (lane >> 2) + h * 8;
                int col = cb * 128 + wn + nf * 8 + ((lane & 3) << 1);
                float v0 = acc[mf][nf][2 * h]     + bias_e[col];
                float v1 = acc[mf][nf][2 * h + 1] + bias_e[col + 1];
                size_t o = (size_t)e * ((size_t)B_ROWS * DIMK)
                         + (size_t)row * DIMK + col;
                if (mode) {
                    v0 = 0.5f * v0 * (1.0f + erff(v0 * 0.70710678118654752f));
                    v1 = 0.5f * v1 * (1.0f + erff(v1 * 0.70710678118654752f));
                    __nv_bfloat16 h0 = __float2bfloat16_rn(v0);
                    __nv_bfloat16 h1 = __float2bfloat16_rn(v1);
                    __nv_bfloat162 ph; ph.x = h0; ph.y = h1;
                    __nv_bfloat162 pl;
                    pl.x = __float2bfloat16_rn(v0 - __bfloat162float(h0));
                    pl.y = __float2bfloat16_rn(v1 - __bfloat162float(h1));
                    *(__nv_bfloat162*)(Ohi + o) = ph;
                    *(__nv_bfloat162*)(Olo + o) = pl;
                } else {
                    float2 v; v.x = v0; v.y = v1;
                    *(float2*)(Of + o) = v;
                }
            }
        }
    }
}

// ---------------------------------------------------------------------------
// LayerNorm + softmax-weighted combine over all experts
// ---------------------------------------------------------------------------
__global__ void ln_combine_kernel(const float* __restrict__ gamma,
                                  const float* __restrict__ beta,
                                  float* __restrict__ out) {
    __shared__ float row[DIMK];
    __shared__ float red[256];
    const int b = blockIdx.x;
    const int tid = threadIdx.x;

    float acc[4] = {0.f, 0.f, 0.f, 0.f};

    for (int e = 0; e < N_EXP; e++) {
        const float* y = g_Y + ((size_t)e * B_ROWS + b) * DIMK;
        float s = 0.f;
#pragma unroll
        for (int i = 0; i < 4; i++) {
            float v = y[tid + 256 * i];
            row[tid + 256 * i] = v;
            s += v;
        }
        red[tid] = s;
        __syncthreads();
        for (int st = 128; st > 0; st >>= 1) {
            if (tid < st) red[tid] += red[tid + st];
            __syncthreads();
        }
        float mu = red[0] * (1.f / DIMK);
        __syncthreads();

        float s2 = 0.f;
#pragma unroll
        for (int i = 0; i < 4; i++) {
            float d = row[tid + 256 * i] - mu;
            s2 += d * d;
        }
        red[tid] = s2;
        __syncthreads();
        for (int st = 128; st > 0; st >>= 1) {
            if (tid < st) red[tid] += red[tid + st];
            __syncthreads();
        }
        float inv = rsqrtf(red[0] * (1.f / DIMK) + 1e-5f);
        float w = g_wts[(size_t)b * N_EXP + e];

#pragma unroll
        for (int i = 0; i < 4; i++) {
            int o = tid + 256 * i;
            acc[i] += w * ((row[o] - mu) * inv * gamma[e * DIMK + o] + beta[e * DIMK + o]);
        }
        __syncthreads();
    }
#pragma unroll
    for (int i = 0; i < 4; i++)
        out[(size_t)b * DIMK + tid + 256 * i] = acc[i];
}

// ---------------------------------------------------------------------------
// Host launch
// ---------------------------------------------------------------------------
extern "C" void kernel_launch(void* const* d_in, const int* in_sizes, int n_in,
                              void* d_out, int out_size)
{
    const float* z_s   = (const float*)d_in[0];
    const float* z_e   = (const float*)d_in[1];
    const float* rw    = (const float*)d_in[2];
    const float* rb    = (const float*)d_in[3];
    const float* w1    = (const float*)d_in[4];
    const float* b1    = (const float*)d_in[5];
    const float* w2    = (const float*)d_in[6];
    const float* b2    = (const float*)d_in[7];
    const float* gamma = (const float*)d_in[8];
    const float* beta  = (const float*)d_in[9];
    float* out = (float*)d_out;

    __nv_bfloat16 *comb_hi, *comb_lo, *w1t_hi, *w1t_lo, *w2t_hi, *w2t_lo, *H_hi, *H_lo;
    float *Y;
    cudaGetSymbolAddress((void**)&comb_hi, g_comb_hi);
    cudaGetSymbolAddress((void**)&comb_lo, g_comb_lo);
    cudaGetSymbolAddress((void**)&w1t_hi, g_w1t_hi);
    cudaGetSymbolAddress((void**)&w1t_lo, g_w1t_lo);
    cudaGetSymbolAddress((void**)&w2t_hi, g_w2t_hi);
    cudaGetSymbolAddress((void**)&w2t_lo, g_w2t_lo);
    cudaGetSymbolAddress((void**)&H_hi, g_H_hi);
    cudaGetSymbolAddress((void**)&H_lo, g_H_lo);
    cudaGetSymbolAddress((void**)&Y, g_Y);

    cudaFuncSetAttribute(gemm_mma_kernel,
                         cudaFuncAttributeMaxDynamicSharedMemorySize, SMEM_BYTES);

    {
        size_t total = (size_t)B_ROWS * DIMK;
        split_comb_kernel<<<(int)((total + 255) / 256), 256>>>(z_s, z_e);
    }
    {
        size_t total = (size_t)N_EXP * DIMK * DIMK;
        int blocks = (int)((total + 255) / 256);
        split_wT_kernel<<<blocks, 256>>>(w1, w1t_hi, w1t_lo);
        split_wT_kernel<<<blocks, 256>>>(w2, w2t_hi, w2t_lo);
    }
    router_kernel<<<B_ROWS, 256>>>(z_s, z_e, rw, rb);

    dim3 grid(8, 128, 8);
    // GEMM1: H = bf16split(gelu(comb @ w1 + b1))
    gemm_mma_kernel<<<grid, 256, SMEM_BYTES>>>(
        comb_hi, comb_lo, (size_t)0,
        w1t_hi, w1t_lo, b1, 1,
        H_hi, H_lo, nullptr);
    // GEMM2: Y = H @ w2 + b2 (fp32)
    gemm_mma_kernel<<<grid, 256, SMEM_BYTES>>>(
        H_hi, H_lo, (size_t)B_ROWS * DIMK,
        w2t_hi, w2t_lo, b2, 0,
        nullptr, nullptr, Y);

    ln_combine_kernel<<<B_ROWS, 256>>>(gamma, beta, out);
}

// round 6
// speedup vs baseline: 3.5700x; 1.2969x over previous
#include <cuda_runtime.h>
#include <cuda_bf16.h>
#include <math.h>
#include <stdint.h>

#define B_ROWS 16384
#define DIMK   1024
#define N_EXP  8

// ---------------------------------------------------------------------------
// Static device scratch (no allocations allowed)
// ---------------------------------------------------------------------------
__device__ __nv_bfloat16 g_comb_hi[(size_t)B_ROWS * DIMK];
__device__ __nv_bfloat16 g_comb_lo[(size_t)B_ROWS * DIMK];
__device__ __nv_bfloat16 g_w1t_hi[(size_t)N_EXP * DIMK * DIMK];   // [e][n][k]
__device__ __nv_bfloat16 g_w1t_lo[(size_t)N_EXP * DIMK * DIMK];
__device__ __nv_bfloat16 g_w2t_hi[(size_t)N_EXP * DIMK * DIMK];
__device__ __nv_bfloat16 g_w2t_lo[(size_t)N_EXP * DIMK * DIMK];
__device__ __nv_bfloat16 g_H_hi[(size_t)N_EXP * B_ROWS * DIMK];   // [e][m][k]
__device__ __nv_bfloat16 g_H_lo[(size_t)N_EXP * B_ROWS * DIMK];
__device__ float         g_Y[(size_t)N_EXP * B_ROWS * DIMK];      // [e][m][n]
__device__ float         g_wts[(size_t)B_ROWS * N_EXP];

// ---------------------------------------------------------------------------
// helpers (sm_80-level PTX only)
// ---------------------------------------------------------------------------
__device__ __forceinline__ void cp16(uint32_t dst, const void* src) {
    asm volatile("cp.async.cg.shared.global [%0], [%1], 16;"
                 :: "r"(dst), "l"(__cvta_generic_to_global(src)) : "memory");
}
__device__ __forceinline__ void ldsm_x4(uint32_t* r, uint32_t addr) {
    asm volatile("ldmatrix.sync.aligned.m8n8.x4.shared.b16 {%0,%1,%2,%3}, [%4];"
                 : "=r"(r[0]), "=r"(r[1]), "=r"(r[2]), "=r"(r[3]) : "r"(addr));
}
__device__ __forceinline__ void mma_bf16(float* d, const uint32_t* a, const uint32_t* b) {
    asm volatile("mma.sync.aligned.m16n8k16.row.col.f32.bf16.bf16.f32 "
                 "{%0,%1,%2,%3}, {%4,%5,%6,%7}, {%8,%9}, {%0,%1,%2,%3};"
                 : "+f"(d[0]), "+f"(d[1]), "+f"(d[2]), "+f"(d[3])
                 : "r"(a[0]), "r"(a[1]), "r"(a[2]), "r"(a[3]), "r"(b[0]), "r"(b[1]));
}
// swizzled byte offset within a [128 rows x 32 bf16] tile (64B rows, 4x16B chunks)
__device__ __forceinline__ uint32_t swz(int r, int c) {
    return (uint32_t)(r * 64 + ((c ^ ((r >> 1) & 3)) << 4));
}

// ---------------------------------------------------------------------------
// Split / transpose kernels
// ---------------------------------------------------------------------------
__global__ void split_comb_kernel(const float* __restrict__ zs,
                                  const float* __restrict__ ze) {
    size_t g = (size_t)blockIdx.x * blockDim.x + threadIdx.x;
    if (g >= (size_t)B_ROWS * DIMK) return;
    size_t b = g >> 10; int i = (int)(g & 1023);
    float v = (i < 512) ? zs[(b << 9) + i] : ze[(b << 9) + i - 512];
    __nv_bfloat16 h = __float2bfloat16_rn(v);
    g_comb_hi[g] = h;
    g_comb_lo[g] = __float2bfloat16_rn(v - __bfloat162float(h));
}

// w: [e][k][n] fp32 -> out: [e][n][k] bf16 hi/lo
__global__ void split_wT_kernel(const float* __restrict__ w,
                                __nv_bfloat16* __restrict__ thi,
                                __nv_bfloat16* __restrict__ tlo) {
    size_t g = (size_t)blockIdx.x * blockDim.x + threadIdx.x;
    if (g >= (size_t)N_EXP * DIMK * DIMK) return;
    size_t e = g >> 20;
    int k = (int)((g >> 10) & 1023);
    int n = (int)(g & 1023);
    float v = w[g];
    size_t o = (e << 20) + ((size_t)n << 10) + k;
    __nv_bfloat16 h = __float2bfloat16_rn(v);
    thi[o] = h;
    tlo[o] = __float2bfloat16_rn(v - __bfloat162float(h));
}

// ---------------------------------------------------------------------------
// Router softmax: warp-per-4-rows, smem-transposed weights, shfl reductions
// grid = B_ROWS/32, block = 256
// ---------------------------------------------------------------------------
__global__ void __launch_bounds__(256) router_kernel(
    const float* __restrict__ zs, const float* __restrict__ ze,
    const float* __restrict__ rw, const float* __restrict__ rb)
{
    __shared__ float rws[N_EXP][DIMK];   // transposed [e][k], 32 KB
    __shared__ float rbs[N_EXP];
    const int tid = threadIdx.x, lane = tid & 31, w = tid >> 5;

    for (int i = tid; i < N_EXP * DIMK; i += 256) {
        int k = i >> 3, e = i & 7;
        rws[e][k] = rw[i];               // rw[k*8+e]
    }
    if (tid < N_EXP) rbs[tid] = rb[tid];
    __syncthreads();

    const int row0 = blockIdx.x * 32 + w * 4;
#pragma unroll 1
    for (int rr = 0; rr < 4; rr++) {
        const int b = row0 + rr;
        float acc[N_EXP];
#pragma unroll
        for (int e = 0; e < N_EXP; e++) acc[e] = 0.f;
#pragma unroll
        for (int j = 0; j < 32; j++) {
            int k = j * 32 + lane;
            float xv = (k < 512) ? zs[(size_t)b * 512 + k]
                                 : ze[(size_t)b * 512 + k - 512];
#pragma unroll
            for (int e = 0; e < N_EXP; e++) acc[e] += xv * rws[e][k];
        }
#pragma unroll
        for (int e = 0; e < N_EXP; e++)
#pragma unroll
            for (int s = 16; s; s >>= 1)
                acc[e] += __shfl_xor_sync(0xffffffffu, acc[e], s);
        if (lane == 0) {
            float mx = -1e30f;
#pragma unroll
            for (int e = 0; e < N_EXP; e++) { acc[e] += rbs[e]; mx = fmaxf(mx, acc[e]); }
            float sum = 0.f;
#pragma unroll
            for (int e = 0; e < N_EXP; e++) { acc[e] = expf(acc[e] - mx); sum += acc[e]; }
            float inv = 1.f / sum;
#pragma unroll
            for (int e = 0; e < N_EXP; e++) g_wts[(size_t)b * N_EXP + e] = acc[e] * inv;
        }
    }
}

// ---------------------------------------------------------------------------
// bf16 mma.sync GEMM with 3-term split, single-barrier pipeline.
// CTA 128x128, BK=32, 3 stages, 8 warps (2x4), warp tile 64x32.
// ---------------------------------------------------------------------------
#define TILE_B   8192
#define STAGE_B  (4 * TILE_B)
#define STAGES   3
#define SMEM_BYTES (STAGES * STAGE_B)    // 96 KB
#define CHUNKS   (DIMK / 32)             // 32

__device__ __forceinline__ void load_chunk(uint32_t stage_base,
                                           const __nv_bfloat16* pAh,
                                           const __nv_bfloat16* pAl,
                                           const __nv_bfloat16* pBh,
                                           const __nv_bfloat16* pBl,
                                           int k0, int tid) {
#pragma unroll
    for (int i = 0; i < 2; i++) {
        int id = tid + i * 256;
        int r = id >> 2;
        int c = id & 3;
        uint32_t o = swz(r, c);
        const size_t s = (size_t)r * DIMK + k0 + c * 8;
        cp16(stage_base + o,              pAh + s);
        cp16(stage_base + TILE_B + o,     pAl + s);
        cp16(stage_base + 2 * TILE_B + o, pBh + s);
        cp16(stage_base + 3 * TILE_B + o, pBl + s);
    }
}

__global__ void __launch_bounds__(256, 2) gemm_mma_kernel(
    const __nv_bfloat16* __restrict__ Ahi, const __nv_bfloat16* __restrict__ Alo,
    size_t a_estride,
    const __nv_bfloat16* __restrict__ Bhi, const __nv_bfloat16* __restrict__ Blo,
    const float* __restrict__ bias, int mode,
    __nv_bfloat16* __restrict__ Ohi, __nv_bfloat16* __restrict__ Olo,
    float* __restrict__ Of)
{
    extern __shared__ char smem[];
    const int tid  = threadIdx.x;
    const int wid  = tid >> 5;
    const int lane = tid & 31;
    const int cb = blockIdx.x;
    const int rb = blockIdx.y;
    const int e  = blockIdx.z;
    const int wm = (wid >> 2) * 64;
    const int wn = (wid & 3) * 32;

    const uint32_t sbase = (uint32_t)__cvta_generic_to_shared(smem);

    const __nv_bfloat16* pAh = Ahi + (size_t)e * a_estride + (size_t)rb * 128 * DIMK;
    const __nv_bfloat16* pAl = Alo + (size_t)e * a_estride + (size_t)rb * 128 * DIMK;
    const __nv_bfloat16* pBh = Bhi + ((size_t)e * DIMK + (size_t)cb * 128) * DIMK;
    const __nv_bfloat16* pBl = Blo + ((size_t)e * DIMK + (size_t)cb * 128) * DIMK;

    float acc[4][4][4];
#pragma unroll
    for (int i = 0; i < 4; i++)
#pragma unroll
        for (int j = 0; j < 4; j++)
#pragma unroll
            for (int k = 0; k < 4; k++) acc[i][j][k] = 0.f;

#pragma unroll
    for (int s = 0; s < STAGES - 1; s++) {
        load_chunk(sbase + s * STAGE_B, pAh, pAl, pBh, pBl, s * 32, tid);
        asm volatile("cp.async.commit_group;" ::: "memory");
    }

    const int jA = lane >> 3;
    const int rA_base = ((jA & 1) << 3) + (lane & 7);
    const int cA_base = jA >> 1;
    const int jB = lane >> 3;
    const int rB_base = ((jB >> 1) << 3) + (lane & 7);
    const int cB_base = jB & 1;

    for (int c = 0; c < CHUNKS; c++) {
        const int pf = c + STAGES - 1;
        // wait for chunk c's group; one barrier both publishes data and
        // protects stage (c-1)%3 (== (pf)%3) from the upcoming overwrite.
        if (pf < CHUNKS) {
            asm volatile("cp.async.wait_group 1;" ::: "memory");
        } else {
            asm volatile("cp.async.wait_group 0;" ::: "memory");
        }
        __syncthreads();
        if (pf < CHUNKS) {
            load_chunk(sbase + (pf % STAGES) * STAGE_B, pAh, pAl, pBh, pBl, pf * 32, tid);
            asm volatile("cp.async.commit_group;" ::: "memory");
        }

        const uint32_t ah_b = sbase + (c % STAGES) * STAGE_B;
        const uint32_t al_b = ah_b + TILE_B;
        const uint32_t bh_b = ah_b + 2 * TILE_B;
        const uint32_t bl_b = ah_b + 3 * TILE_B;

#pragma unroll
        for (int ks = 0; ks < 2; ks++) {
            const int kc0 = ks * 2;
            uint32_t bh[4][2], bl[4][2];
#pragma unroll
            for (int q = 0; q < 2; q++) {
                int rB = wn + q * 16 + rB_base;
                int cB = kc0 + cB_base;
                uint32_t o = swz(rB, cB);
                uint32_t t[4];
                ldsm_x4(t, bh_b + o);
                bh[2 * q][0] = t[0]; bh[2 * q][1] = t[1];
                bh[2 * q + 1][0] = t[2]; bh[2 * q + 1][1] = t[3];
                ldsm_x4(t, bl_b + o);
                bl[2 * q][0] = t[0]; bl[2 * q][1] = t[1];
                bl[2 * q + 1][0] = t[2]; bl[2 * q + 1][1] = t[3];
            }
#pragma unroll
            for (int mf = 0; mf < 4; mf++) {
                int rA = wm + mf * 16 + rA_base;
                int cA = kc0 + cA_base;
                uint32_t o = swz(rA, cA);
                uint32_t ah[4], al[4];
                ldsm_x4(ah, ah_b + o);
                ldsm_x4(al, al_b + o);
#pragma unroll
                for (int nf = 0; nf < 4; nf++) {
                    mma_bf16(acc[mf][nf], ah, bh[nf]);
                    mma_bf16(acc[mf][nf], ah, bl[nf]);
                    mma_bf16(acc[mf][nf], al, bh[nf]);
                }
            }
        }
    }

    // --------------------------- epilogue ---------------------------
    const float* bias_e = bias + (size_t)e * DIMK;
#pragma unroll
    for (int mf = 0; mf < 4; mf++) {
#pragma unroll
        for (int nf = 0; nf < 4; nf++) {
#pragma unroll
            for (int h = 0; h < 2; h++) {
                int row = rb * 128 + wm + mf * 16 + (lane >> 2) + h * 8;
                int col = cb * 128 + wn + nf * 8 + ((lane & 3) << 1);
                float v0 = acc[mf][nf][2 * h]     + bias_e[col];
                float v1 = acc[mf][nf][2 * h + 1] + bias_e[col + 1];
                size_t o = (size_t)e * ((size_t)B_ROWS * DIMK)
                         + (size_t)row * DIMK + col;
                if (mode) {
                    v0 = 0.5f * v0 * (1.0f + erff(v0 * 0.70710678118654752f));
                    v1 = 0.5f * v1 * (1.0f + erff(v1 * 0.70710678118654752f));
                    __nv_bfloat16 h0 = __float2bfloat16_rn(v0);
                    __nv_bfloat16 h1 = __float2bfloat16_rn(v1);
                    __nv_bfloat162 ph; ph.x = h0; ph.y = h1;
                    __nv_bfloat162 pl;
                    pl.x = __float2bfloat16_rn(v0 - __bfloat162float(h0));
                    pl.y = __float2bfloat16_rn(v1 - __bfloat162float(h1));
                    *(__nv_bfloat162*)(Ohi + o) = ph;
                    *(__nv_bfloat162*)(Olo + o) = pl;
                } else {
                    float2 v; v.x = v0; v.y = v1;
                    *(float2*)(Of + o) = v;
                }
            }
        }
    }
}

// ---------------------------------------------------------------------------
// LayerNorm + combine: warp-per-expert, shfl reductions, one barrier.
// grid = B_ROWS, block = 256 (8 warps = 8 experts)
// ---------------------------------------------------------------------------
__global__ void __launch_bounds__(256) ln_combine_kernel(
    const float* __restrict__ gamma, const float* __restrict__ beta,
    float* __restrict__ out)
{
    __shared__ float ybuf[N_EXP][DIMK];    // 32 KB
    const int b = blockIdx.x;
    const int tid = threadIdx.x;
    const int e = tid >> 5;
    const int lane = tid & 31;

    const float4* y4 = (const float4*)(g_Y + ((size_t)e * B_ROWS + b) * DIMK);
    float4 v[8];
    float s = 0.f;
#pragma unroll
    for (int j = 0; j < 8; j++) {
        v[j] = y4[j * 32 + lane];
        s += v[j].x + v[j].y + v[j].z + v[j].w;
    }
#pragma unroll
    for (int st = 16; st; st >>= 1) s += __shfl_xor_sync(0xffffffffu, s, st);
    const float mu = s * (1.f / DIMK);

    float s2 = 0.f;
#pragma unroll
    for (int j = 0; j < 8; j++) {
        float dx = v[j].x - mu, dy = v[j].y - mu, dz = v[j].z - mu, dw = v[j].w - mu;
        s2 += dx * dx + dy * dy + dz * dz + dw * dw;
    }
#pragma unroll
    for (int st = 16; st; st >>= 1) s2 += __shfl_xor_sync(0xffffffffu, s2, st);
    const float inv = rsqrtf(s2 * (1.f / DIMK) + 1e-5f);
    const float wgt = g_wts[(size_t)b * N_EXP + e];

    const float4* g4 = (const float4*)(gamma + (size_t)e * DIMK);
    const float4* b4 = (const float4*)(beta + (size_t)e * DIMK);
#pragma unroll
    for (int j = 0; j < 8; j++) {
        int c4 = j * 32 + lane;
        float4 gg = g4[c4], bb = b4[c4], r;
        r.x = wgt * ((v[j].x - mu) * inv * gg.x + bb.x);
        r.y = wgt * ((v[j].y - mu) * inv * gg.y + bb.y);
        r.z = wgt * ((v[j].z - mu) * inv * gg.z + bb.z);
        r.w = wgt * ((v[j].w - mu) * inv * gg.w + bb.w);
        *(float4*)&ybuf[e][c4 * 4] = r;
    }
    __syncthreads();

    float4 a = *(float4*)&ybuf[0][tid * 4];
#pragma unroll
    for (int ee = 1; ee < N_EXP; ee++) {
        float4 u = *(float4*)&ybuf[ee][tid * 4];
        a.x += u.x; a.y += u.y; a.z += u.z; a.w += u.w;
    }
    *(float4*)(out + (size_t)b * DIMK + tid * 4) = a;
}

// ---------------------------------------------------------------------------
// Host launch
// ---------------------------------------------------------------------------
extern "C" void kernel_launch(void* const* d_in, const int* in_sizes, int n_in,
                              void* d_out, int out_size)
{
    const float* z_s   = (const float*)d_in[0];
    const float* z_e   = (const float*)d_in[1];
    const float* rw    = (const float*)d_in[2];
    const float* rb    = (const float*)d_in[3];
    const float* w1    = (const float*)d_in[4];
    const float* b1    = (const float*)d_in[5];
    const float* w2    = (const float*)d_in[6];
    const float* b2    = (const float*)d_in[7];
    const float* gamma = (const float*)d_in[8];
    const float* beta  = (const float*)d_in[9];
    float* out = (float*)d_out;

    __nv_bfloat16 *comb_hi, *comb_lo, *w1t_hi, *w1t_lo, *w2t_hi, *w2t_lo, *H_hi, *H_lo;
    float *Y;
    cudaGetSymbolAddress((void**)&comb_hi, g_comb_hi);
    cudaGetSymbolAddress((void**)&comb_lo, g_comb_lo);
    cudaGetSymbolAddress((void**)&w1t_hi, g_w1t_hi);
    cudaGetSymbolAddress((void**)&w1t_lo, g_w1t_lo);
    cudaGetSymbolAddress((void**)&w2t_hi, g_w2t_hi);
    cudaGetSymbolAddress((void**)&w2t_lo, g_w2t_lo);
    cudaGetSymbolAddress((void**)&H_hi, g_H_hi);
    cudaGetSymbolAddress((void**)&H_lo, g_H_lo);
    cudaGetSymbolAddress((void**)&Y, g_Y);

    cudaFuncSetAttribute(gemm_mma_kernel,
                         cudaFuncAttributeMaxDynamicSharedMemorySize, SMEM_BYTES);

    {
        size_t total = (size_t)B_ROWS * DIMK;
        split_comb_kernel<<<(int)((total + 255) / 256), 256>>>(z_s, z_e);
    }
    {
        size_t total = (size_t)N_EXP * DIMK * DIMK;
        int blocks = (int)((total + 255) / 256);
        split_wT_kernel<<<blocks, 256>>>(w1, w1t_hi, w1t_lo);
        split_wT_kernel<<<blocks, 256>>>(w2, w2t_hi, w2t_lo);
    }
    router_kernel<<<B_ROWS / 32, 256>>>(z_s, z_e, rw, rb);

    dim3 grid(8, 128, 8);
    gemm_mma_kernel<<<grid, 256, SMEM_BYTES>>>(
        comb_hi, comb_lo, (size_t)0,
        w1t_hi, w1t_lo, b1, 1,
        H_hi, H_lo, nullptr);
    gemm_mma_kernel<<<grid, 256, SMEM_BYTES>>>(
        H_hi, H_lo, (size_t)B_ROWS * DIMK,
        w2t_hi, w2t_lo, b2, 0,
        nullptr, nullptr, Y);

    ln_combine_kernel<<<B_ROWS, 256>>>(gamma, beta, out);
}

// round 7
// speedup vs baseline: 3.9788x; 1.1145x over previous
#include <cuda_runtime.h>
#include <cuda_bf16.h>
#include <math.h>
#include <stdint.h>

#define B_ROWS 16384
#define DIMK   1024
#define N_EXP  8

// ---------------------------------------------------------------------------
// Static device scratch (no allocations allowed)
// ---------------------------------------------------------------------------
__device__ __nv_bfloat16 g_comb_hi[(size_t)B_ROWS * DIMK];
__device__ __nv_bfloat16 g_comb_lo[(size_t)B_ROWS * DIMK];
__device__ __nv_bfloat16 g_w1t_hi[(size_t)N_EXP * DIMK * DIMK];   // [e][n][k]
__device__ __nv_bfloat16 g_w1t_lo[(size_t)N_EXP * DIMK * DIMK];
__device__ __nv_bfloat16 g_w2t_hi[(size_t)N_EXP * DIMK * DIMK];
__device__ __nv_bfloat16 g_w2t_lo[(size_t)N_EXP * DIMK * DIMK];
__device__ __nv_bfloat16 g_H_hi[(size_t)N_EXP * B_ROWS * DIMK];   // [e][m][k]
__device__ __nv_bfloat16 g_H_lo[(size_t)N_EXP * B_ROWS * DIMK];
__device__ float         g_Y[(size_t)N_EXP * B_ROWS * DIMK];      // [e][m][n]
__device__ float         g_wts[(size_t)B_ROWS * N_EXP];

// ---------------------------------------------------------------------------
// helpers (sm_80-level PTX only)
// ---------------------------------------------------------------------------
__device__ __forceinline__ void cp16(uint32_t dst, const void* src) {
    asm volatile("cp.async.cg.shared.global [%0], [%1], 16;"
                 :: "r"(dst), "l"(__cvta_generic_to_global(src)) : "memory");
}
__device__ __forceinline__ void ldsm_x4(uint32_t* r, uint32_t addr) {
    asm volatile("ldmatrix.sync.aligned.m8n8.x4.shared.b16 {%0,%1,%2,%3}, [%4];"
                 : "=r"(r[0]), "=r"(r[1]), "=r"(r[2]), "=r"(r[3]) : "r"(addr));
}
__device__ __forceinline__ void mma_bf16(float* d, const uint32_t* a, const uint32_t* b) {
    asm volatile("mma.sync.aligned.m16n8k16.row.col.f32.bf16.bf16.f32 "
                 "{%0,%1,%2,%3}, {%4,%5,%6,%7}, {%8,%9}, {%0,%1,%2,%3};"
                 : "+f"(d[0]), "+f"(d[1]), "+f"(d[2]), "+f"(d[3])
                 : "r"(a[0]), "r"(a[1]), "r"(a[2]), "r"(a[3]), "r"(b[0]), "r"(b[1]));
}
// swizzled byte offset within a [128 rows x 32 bf16] tile (64B rows, 4x16B chunks)
__device__ __forceinline__ uint32_t swz(int r, int c) {
    return (uint32_t)(r * 64 + ((c ^ ((r >> 1) & 3)) << 4));
}

// ---------------------------------------------------------------------------
// Split / transpose kernels
// ---------------------------------------------------------------------------
__global__ void split_comb_kernel(const float* __restrict__ zs,
                                  const float* __restrict__ ze) {
    size_t g = (size_t)blockIdx.x * blockDim.x + threadIdx.x;
    if (g >= (size_t)B_ROWS * DIMK) return;
    size_t b = g >> 10; int i = (int)(g & 1023);
    float v = (i < 512) ? zs[(b << 9) + i] : ze[(b << 9) + i - 512];
    __nv_bfloat16 h = __float2bfloat16_rn(v);
    g_comb_hi[g] = h;
    g_comb_lo[g] = __float2bfloat16_rn(v - __bfloat162float(h));
}

// w: [e][k][n] fp32 -> out: [e][n][k] bf16 hi/lo; smem-tiled 64x64 transpose
// grid (16, 16, 8), block 256
__global__ void __launch_bounds__(256) split_wT_kernel(
    const float* __restrict__ w,
    __nv_bfloat16* __restrict__ thi, __nv_bfloat16* __restrict__ tlo)
{
    __shared__ float s[64][65];
    const int tid = threadIdx.x;
    const int tk = blockIdx.y * 64, tn = blockIdx.x * 64;
    const size_t eo = (size_t)blockIdx.z << 20;

#pragma unroll
    for (int i = 0; i < 16; i++) {
        int idx = tid + i * 256;
        int kk = idx >> 6, nn = idx & 63;
        s[kk][nn] = w[eo + (size_t)(tk + kk) * DIMK + tn + nn];
    }
    __syncthreads();
#pragma unroll
    for (int i = 0; i < 16; i++) {
        int idx = tid + i * 256;
        int nn = idx >> 6, kk = idx & 63;
        float v = s[kk][nn];
        __nv_bfloat16 h = __float2bfloat16_rn(v);
        size_t o = eo + (size_t)(tn + nn) * DIMK + tk + kk;
        thi[o] = h;
        tlo[o] = __float2bfloat16_rn(v - __bfloat162float(h));
    }
}

// ---------------------------------------------------------------------------
// Router softmax: warp-per-4-rows, smem-transposed weights, shfl reductions
// ---------------------------------------------------------------------------
__global__ void __launch_bounds__(256) router_kernel(
    const float* __restrict__ zs, const float* __restrict__ ze,
    const float* __restrict__ rw, const float* __restrict__ rb)
{
    __shared__ float rws[N_EXP][DIMK];
    __shared__ float rbs[N_EXP];
    const int tid = threadIdx.x, lane = tid & 31, w = tid >> 5;

    for (int i = tid; i < N_EXP * DIMK; i += 256) {
        int k = i >> 3, e = i & 7;
        rws[e][k] = rw[i];
    }
    if (tid < N_EXP) rbs[tid] = rb[tid];
    __syncthreads();

    const int row0 = blockIdx.x * 32 + w * 4;
#pragma unroll 1
    for (int rr = 0; rr < 4; rr++) {
        const int b = row0 + rr;
        float acc[N_EXP];
#pragma unroll
        for (int e = 0; e < N_EXP; e++) acc[e] = 0.f;
#pragma unroll
        for (int j = 0; j < 32; j++) {
            int k = j * 32 + lane;
            float xv = (k < 512) ? zs[(size_t)b * 512 + k]
                                 : ze[(size_t)b * 512 + k - 512];
#pragma unroll
            for (int e = 0; e < N_EXP; e++) acc[e] += xv * rws[e][k];
        }
#pragma unroll
        for (int e = 0; e < N_EXP; e++)
#pragma unroll
            for (int s = 16; s; s >>= 1)
                acc[e] += __shfl_xor_sync(0xffffffffu, acc[e], s);
        if (lane == 0) {
            float mx = -1e30f;
#pragma unroll
            for (int e = 0; e < N_EXP; e++) { acc[e] += rbs[e]; mx = fmaxf(mx, acc[e]); }
            float sum = 0.f;
#pragma unroll
            for (int e = 0; e < N_EXP; e++) { acc[e] = expf(acc[e] - mx); sum += acc[e]; }
            float inv = 1.f / sum;
#pragma unroll
            for (int e = 0; e < N_EXP; e++) g_wts[(size_t)b * N_EXP + e] = acc[e] * inv;
        }
    }
}

// ---------------------------------------------------------------------------
// bf16 mma.sync GEMM, 3-term split, single-barrier pipeline.
// CTA 128x128, BK=32, 3 stages, **4 warps (2x2), warp tile 64x64**.
// LDSM read traffic per chunk: 2*A + 2*B = 64KB (was 96KB at 8 warps).
// ---------------------------------------------------------------------------
#define TILE_B   8192
#define STAGE_B  (4 * TILE_B)
#define STAGES   3
#define SMEM_BYTES (STAGES * STAGE_B)    // 96 KB
#define CHUNKS   (DIMK / 32)             // 32

__device__ __forceinline__ void load_chunk(uint32_t stage_base,
                                           const __nv_bfloat16* pAh,
                                           const __nv_bfloat16* pAl,
                                           const __nv_bfloat16* pBh,
                                           const __nv_bfloat16* pBl,
                                           int k0, int tid) {
#pragma unroll
    for (int i = 0; i < 4; i++) {
        int id = tid + i * 128;          // 0..511
        int r = id >> 2;
        int c = id & 3;
        uint32_t o = swz(r, c);
        const size_t s = (size_t)r * DIMK + k0 + c * 8;
        cp16(stage_base + o,              pAh + s);
        cp16(stage_base + TILE_B + o,     pAl + s);
        cp16(stage_base + 2 * TILE_B + o, pBh + s);
        cp16(stage_base + 3 * TILE_B + o, pBl + s);
    }
}

__global__ void __launch_bounds__(128, 2) gemm_mma_kernel(
    const __nv_bfloat16* __restrict__ Ahi, const __nv_bfloat16* __restrict__ Alo,
    size_t a_estride,
    const __nv_bfloat16* __restrict__ Bhi, const __nv_bfloat16* __restrict__ Blo,
    const float* __restrict__ bias, int mode,
    __nv_bfloat16* __restrict__ Ohi, __nv_bfloat16* __restrict__ Olo,
    float* __restrict__ Of)
{
    extern __shared__ char smem[];
    const int tid  = threadIdx.x;
    const int wid  = tid >> 5;
    const int lane = tid & 31;
    const int cb = blockIdx.x;
    const int rb = blockIdx.y;
    const int e  = blockIdx.z;
    const int wm = (wid >> 1) * 64;     // 0 / 64
    const int wn = (wid & 1) * 64;      // 0 / 64

    const uint32_t sbase = (uint32_t)__cvta_generic_to_shared(smem);

    const __nv_bfloat16* pAh = Ahi + (size_t)e * a_estride + (size_t)rb * 128 * DIMK;
    const __nv_bfloat16* pAl = Alo + (size_t)e * a_estride + (size_t)rb * 128 * DIMK;
    const __nv_bfloat16* pBh = Bhi + ((size_t)e * DIMK + (size_t)cb * 128) * DIMK;
    const __nv_bfloat16* pBl = Blo + ((size_t)e * DIMK + (size_t)cb * 128) * DIMK;

    float acc[4][8][4];
#pragma unroll
    for (int i = 0; i < 4; i++)
#pragma unroll
        for (int j = 0; j < 8; j++)
#pragma unroll
            for (int k = 0; k < 4; k++) acc[i][j][k] = 0.f;

#pragma unroll
    for (int s = 0; s < STAGES - 1; s++) {
        load_chunk(sbase + s * STAGE_B, pAh, pAl, pBh, pBl, s * 32, tid);
        asm volatile("cp.async.commit_group;" ::: "memory");
    }

    const int jA = lane >> 3;
    const int rA_base = ((jA & 1) << 3) + (lane & 7);
    const int cA_base = jA >> 1;
    const int jB = lane >> 3;
    const int rB_base = ((jB >> 1) << 3) + (lane & 7);
    const int cB_base = jB & 1;

    for (int c = 0; c < CHUNKS; c++) {
        const int pf = c + STAGES - 1;
        if (pf < CHUNKS) {
            asm volatile("cp.async.wait_group 1;" ::: "memory");
        } else {
            asm volatile("cp.async.wait_group 0;" ::: "memory");
        }
        __syncthreads();
        if (pf < CHUNKS) {
            load_chunk(sbase + (pf % STAGES) * STAGE_B, pAh, pAl, pBh, pBl, pf * 32, tid);
            asm volatile("cp.async.commit_group;" ::: "memory");
        }

        const uint32_t ah_b = sbase + (c % STAGES) * STAGE_B;
        const uint32_t al_b = ah_b + TILE_B;
        const uint32_t bh_b = ah_b + 2 * TILE_B;
        const uint32_t bl_b = ah_b + 3 * TILE_B;

#pragma unroll
        for (int ks = 0; ks < 2; ks++) {
            const int kc0 = ks * 2;
            uint32_t bh[8][2], bl[8][2];
#pragma unroll
            for (int q = 0; q < 4; q++) {
                int rB = wn + q * 16 + rB_base;
                int cB = kc0 + cB_base;
                uint32_t o = swz(rB, cB);
                uint32_t t[4];
                ldsm_x4(t, bh_b + o);
                bh[2 * q][0] = t[0]; bh[2 * q][1] = t[1];
                bh[2 * q + 1][0] = t[2]; bh[2 * q + 1][1] = t[3];
                ldsm_x4(t, bl_b + o);
                bl[2 * q][0] = t[0]; bl[2 * q][1] = t[1];
                bl[2 * q + 1][0] = t[2]; bl[2 * q + 1][1] = t[3];
            }
#pragma unroll
            for (int mf = 0; mf < 4; mf++) {
                int rA = wm + mf * 16 + rA_base;
                int cA = kc0 + cA_base;
                uint32_t o = swz(rA, cA);
                uint32_t ah[4], al[4];
                ldsm_x4(ah, ah_b + o);
                ldsm_x4(al, al_b + o);
#pragma unroll
                for (int nf = 0; nf < 8; nf++) {
                    mma_bf16(acc[mf][nf], ah, bh[nf]);
                    mma_bf16(acc[mf][nf], ah, bl[nf]);
                    mma_bf16(acc[mf][nf], al, bh[nf]);
                }
            }
        }
    }

    // --------------------------- epilogue ---------------------------
    const float* bias_e = bias + (size_t)e * DIMK;
#pragma unroll
    for (int mf = 0; mf < 4; mf++) {
#pragma unroll
        for (int nf = 0; nf < 8; nf++) {
#pragma unroll
            for (int h = 0; h < 2; h++) {
                int row = rb * 128 + wm + mf * 16 + (lane >> 2) + h * 8;
                int col = cb * 128 + wn + nf * 8 + ((lane & 3) << 1);
                float v0 = acc[mf][nf][2 * h]     + bias_e[col];
                float v1 = acc[mf][nf][2 * h + 1] + bias_e[col + 1];
                size_t o = (size_t)e * ((size_t)B_ROWS * DIMK)
                         + (size_t)row * DIMK + col;
                if (mode) {
                    v0 = 0.5f * v0 * (1.0f + erff(v0 * 0.70710678118654752f));
                    v1 = 0.5f * v1 * (1.0f + erff(v1 * 0.70710678118654752f));
                    __nv_bfloat16 h0 = __float2bfloat16_rn(v0);
                    __nv_bfloat16 h1 = __float2bfloat16_rn(v1);
                    __nv_bfloat162 ph; ph.x = h0; ph.y = h1;
                    __nv_bfloat162 pl;
                    pl.x = __float2bfloat16_rn(v0 - __bfloat162float(h0));
                    pl.y = __float2bfloat16_rn(v1 - __bfloat162float(h1));
                    *(__nv_bfloat162*)(Ohi + o) = ph;
                    *(__nv_bfloat162*)(Olo + o) = pl;
                } else {
                    float2 v; v.x = v0; v.y = v1;
                    *(float2*)(Of + o) = v;
                }
            }
        }
    }
}

// ---------------------------------------------------------------------------
// LayerNorm + combine: warp-per-expert, shfl reductions, one barrier.
// ---------------------------------------------------------------------------
__global__ void __launch_bounds__(256) ln_combine_kernel(
    const float* __restrict__ gamma, const float* __restrict__ beta,
    float* __restrict__ out)
{
    __shared__ float ybuf[N_EXP][DIMK];
    const int b = blockIdx.x;
    const int tid = threadIdx.x;
    const int e = tid >> 5;
    const int lane = tid & 31;

    const float4* y4 = (const float4*)(g_Y + ((size_t)e * B_ROWS + b) * DIMK);
    float4 v[8];
    float s = 0.f;
#pragma unroll
    for (int j = 0; j < 8; j++) {
        v[j] = y4[j * 32 + lane];
        s += v[j].x + v[j].y + v[j].z + v[j].w;
    }
#pragma unroll
    for (int st = 16; st; st >>= 1) s += __shfl_xor_sync(0xffffffffu, s, st);
    const float mu = s * (1.f / DIMK);

    float s2 = 0.f;
#pragma unroll
    for (int j = 0; j < 8; j++) {
        float dx = v[j].x - mu, dy = v[j].y - mu, dz = v[j].z - mu, dw = v[j].w - mu;
        s2 += dx * dx + dy * dy + dz * dz + dw * dw;
    }
#pragma unroll
    for (int st = 16; st; st >>= 1) s2 += __shfl_xor_sync(0xffffffffu, s2, st);
    const float inv = rsqrtf(s2 * (1.f / DIMK) + 1e-5f);
    const float wgt = g_wts[(size_t)b * N_EXP + e];

    const float4* g4 = (const float4*)(gamma + (size_t)e * DIMK);
    const float4* b4 = (const float4*)(beta + (size_t)e * DIMK);
#pragma unroll
    for (int j = 0; j < 8; j++) {
        int c4 = j * 32 + lane;
        float4 gg = g4[c4], bb = b4[c4], r;
        r.x = wgt * ((v[j].x - mu) * inv * gg.x + bb.x);
        r.y = wgt * ((v[j].y - mu) * inv * gg.y + bb.y);
        r.z = wgt * ((v[j].z - mu) * inv * gg.z + bb.z);
        r.w = wgt * ((v[j].w - mu) * inv * gg.w + bb.w);
        *(float4*)&ybuf[e][c4 * 4] = r;
    }
    __syncthreads();

    float4 a = *(float4*)&ybuf[0][tid * 4];
#pragma unroll
    for (int ee = 1; ee < N_EXP; ee++) {
        float4 u = *(float4*)&ybuf[ee][tid * 4];
        a.x += u.x; a.y += u.y; a.z += u.z; a.w += u.w;
    }
    *(float4*)(out + (size_t)b * DIMK + tid * 4) = a;
}

// ---------------------------------------------------------------------------
// Host launch
// ---------------------------------------------------------------------------
extern "C" void kernel_launch(void* const* d_in, const int* in_sizes, int n_in,
                              void* d_out, int out_size)
{
    const float* z_s   = (const float*)d_in[0];
    const float* z_e   = (const float*)d_in[1];
    const float* rw    = (const float*)d_in[2];
    const float* rb    = (const float*)d_in[3];
    const float* w1    = (const float*)d_in[4];
    const float* b1    = (const float*)d_in[5];
    const float* w2    = (const float*)d_in[6];
    const float* b2    = (const float*)d_in[7];
    const float* gamma = (const float*)d_in[8];
    const float* beta  = (const float*)d_in[9];
    float* out = (float*)d_out;

    __nv_bfloat16 *comb_hi, *comb_lo, *w1t_hi, *w1t_lo, *w2t_hi, *w2t_lo, *H_hi, *H_lo;
    float *Y;
    cudaGetSymbolAddress((void**)&comb_hi, g_comb_hi);
    cudaGetSymbolAddress((void**)&comb_lo, g_comb_lo);
    cudaGetSymbolAddress((void**)&w1t_hi, g_w1t_hi);
    cudaGetSymbolAddress((void**)&w1t_lo, g_w1t_lo);
    cudaGetSymbolAddress((void**)&w2t_hi, g_w2t_hi);
    cudaGetSymbolAddress((void**)&w2t_lo, g_w2t_lo);
    cudaGetSymbolAddress((void**)&H_hi, g_H_hi);
    cudaGetSymbolAddress((void**)&H_lo, g_H_lo);
    cudaGetSymbolAddress((void**)&Y, g_Y);

    cudaFuncSetAttribute(gemm_mma_kernel,
                         cudaFuncAttributeMaxDynamicSharedMemorySize, SMEM_BYTES);

    {
        size_t total = (size_t)B_ROWS * DIMK;
        split_comb_kernel<<<(int)((total + 255) / 256), 256>>>(z_s, z_e);
    }
    {
        dim3 tg(16, 16, 8);
        split_wT_kernel<<<tg, 256>>>(w1, w1t_hi, w1t_lo);
        split_wT_kernel<<<tg, 256>>>(w2, w2t_hi, w2t_lo);
    }
    router_kernel<<<B_ROWS / 32, 256>>>(z_s, z_e, rw, rb);

    dim3 grid(8, 128, 8);
    gemm_mma_kernel<<<grid, 128, SMEM_BYTES>>>(
        comb_hi, comb_lo, (size_t)0,
        w1t_hi, w1t_lo, b1, 1,
        H_hi, H_lo, nullptr);
    gemm_mma_kernel<<<grid, 128, SMEM_BYTES>>>(
        H_hi, H_lo, (size_t)B_ROWS * DIMK,
        w2t_hi, w2t_lo, b2, 0,
        nullptr, nullptr, Y);

    ln_combine_kernel<<<B_ROWS, 256>>>(gamma, beta, out);
}

// round 8
// speedup vs baseline: 5.1364x; 1.2909x over previous
#include <cuda_runtime.h>
#include <cuda_fp16.h>
#include <math.h>
#include <stdint.h>

#define B_ROWS 16384
#define DIMK   1024
#define N_EXP  8

// ---------------------------------------------------------------------------
// Static device scratch (no allocations allowed)
// ---------------------------------------------------------------------------
__device__ __half g_comb_hi[(size_t)B_ROWS * DIMK];
__device__ __half g_comb_lo[(size_t)B_ROWS * DIMK];
__device__ __half g_w1t[(size_t)N_EXP * DIMK * DIMK];     // [e][n][k] fp16
__device__ __half g_w2t[(size_t)N_EXP * DIMK * DIMK];
__device__ __half g_H_hi[(size_t)N_EXP * B_ROWS * DIMK];  // [e][m][k]
__device__ __half g_H_lo[(size_t)N_EXP * B_ROWS * DIMK];
__device__ float  g_Y[(size_t)N_EXP * B_ROWS * DIMK];     // [e][m][n]
__device__ float  g_wts[(size_t)B_ROWS * N_EXP];

// ---------------------------------------------------------------------------
// helpers (sm_80-level PTX only)
// ---------------------------------------------------------------------------
__device__ __forceinline__ void cp16(uint32_t dst, const void* src) {
    asm volatile("cp.async.cg.shared.global [%0], [%1], 16;"
                 :: "r"(dst), "l"(__cvta_generic_to_global(src)) : "memory");
}
__device__ __forceinline__ void ldsm_x4(uint32_t* r, uint32_t addr) {
    asm volatile("ldmatrix.sync.aligned.m8n8.x4.shared.b16 {%0,%1,%2,%3}, [%4];"
                 : "=r"(r[0]), "=r"(r[1]), "=r"(r[2]), "=r"(r[3]) : "r"(addr));
}
__device__ __forceinline__ void mma_f16(float* d, const uint32_t* a, const uint32_t* b) {
    asm volatile("mma.sync.aligned.m16n8k16.row.col.f32.f16.f16.f32 "
                 "{%0,%1,%2,%3}, {%4,%5,%6,%7}, {%8,%9}, {%0,%1,%2,%3};"
                 : "+f"(d[0]), "+f"(d[1]), "+f"(d[2]), "+f"(d[3])
                 : "r"(a[0]), "r"(a[1]), "r"(a[2]), "r"(a[3]), "r"(b[0]), "r"(b[1]));
}
// swizzled byte offset within a [128 rows x 32 fp16] tile (64B rows, 4x16B chunks)
__device__ __forceinline__ uint32_t swz(int r, int c) {
    return (uint32_t)(r * 64 + ((c ^ ((r >> 1) & 3)) << 4));
}

// ---------------------------------------------------------------------------
// Split / transpose kernels
// ---------------------------------------------------------------------------
__global__ void split_comb_kernel(const float* __restrict__ zs,
                                  const float* __restrict__ ze) {
    size_t g = (size_t)blockIdx.x * blockDim.x + threadIdx.x;
    if (g >= (size_t)B_ROWS * DIMK) return;
    size_t b = g >> 10; int i = (int)(g & 1023);
    float v = (i < 512) ? zs[(b << 9) + i] : ze[(b << 9) + i - 512];
    __half h = __float2half_rn(v);
    g_comb_hi[g] = h;
    g_comb_lo[g] = __float2half_rn(v - __half2float(h));
}

// w: [e][k][n] fp32 -> out: [e][n][k] fp16 (single); smem-tiled 64x64 transpose
// grid (16, 16, 8), block 256
__global__ void __launch_bounds__(256) split_wT_kernel(
    const float* __restrict__ w, __half* __restrict__ t)
{
    __shared__ float s[64][65];
    const int tid = threadIdx.x;
    const int tk = blockIdx.y * 64, tn = blockIdx.x * 64;
    const size_t eo = (size_t)blockIdx.z << 20;

#pragma unroll
    for (int i = 0; i < 16; i++) {
        int idx = tid + i * 256;
        int kk = idx >> 6, nn = idx & 63;
        s[kk][nn] = w[eo + (size_t)(tk + kk) * DIMK + tn + nn];
    }
    __syncthreads();
#pragma unroll
    for (int i = 0; i < 16; i++) {
        int idx = tid + i * 256;
        int nn = idx >> 6, kk = idx & 63;
        t[eo + (size_t)(tn + nn) * DIMK + tk + kk] = __float2half_rn(s[kk][nn]);
    }
}

// ---------------------------------------------------------------------------
// Router softmax: warp-per-4-rows, smem-transposed weights, shfl reductions
// ---------------------------------------------------------------------------
__global__ void __launch_bounds__(256) router_kernel(
    const float* __restrict__ zs, const float* __restrict__ ze,
    const float* __restrict__ rw, const float* __restrict__ rb)
{
    __shared__ float rws[N_EXP][DIMK];
    __shared__ float rbs[N_EXP];
    const int tid = threadIdx.x, lane = tid & 31, w = tid >> 5;

    for (int i = tid; i < N_EXP * DIMK; i += 256) {
        int k = i >> 3, e = i & 7;
        rws[e][k] = rw[i];
    }
    if (tid < N_EXP) rbs[tid] = rb[tid];
    __syncthreads();

    const int row0 = blockIdx.x * 32 + w * 4;
#pragma unroll 1
    for (int rr = 0; rr < 4; rr++) {
        const int b = row0 + rr;
        float acc[N_EXP];
#pragma unroll
        for (int e = 0; e < N_EXP; e++) acc[e] = 0.f;
#pragma unroll
        for (int j = 0; j < 32; j++) {
            int k = j * 32 + lane;
            float xv = (k < 512) ? zs[(size_t)b * 512 + k]
                                 : ze[(size_t)b * 512 + k - 512];
#pragma unroll
            for (int e = 0; e < N_EXP; e++) acc[e] += xv * rws[e][k];
        }
#pragma unroll
        for (int e = 0; e < N_EXP; e++)
#pragma unroll
            for (int s = 16; s; s >>= 1)
                acc[e] += __shfl_xor_sync(0xffffffffu, acc[e], s);
        if (lane == 0) {
            float mx = -1e30f;
#pragma unroll
            for (int e = 0; e < N_EXP; e++) { acc[e] += rbs[e]; mx = fmaxf(mx, acc[e]); }
            float sum = 0.f;
#pragma unroll
            for (int e = 0; e < N_EXP; e++) { acc[e] = expf(acc[e] - mx); sum += acc[e]; }
            float inv = 1.f / sum;
#pragma unroll
            for (int e = 0; e < N_EXP; e++) g_wts[(size_t)b * N_EXP + e] = acc[e] * inv;
        }
    }
}

// ---------------------------------------------------------------------------
// fp16 mma.sync GEMM, 2-term split (Ahi@B + Alo@B), single-barrier pipeline.
// CTA 128x128, BK=32, 4 stages, 4 warps (2x2), warp tile 64x64.
// ---------------------------------------------------------------------------
#define TILE_B   8192
#define STAGE_B  (3 * TILE_B)            // Ah, Al, B
#define STAGES   4
#define SMEM_BYTES (STAGES * STAGE_B)    // 96 KB
#define CHUNKS   (DIMK / 32)             // 32

__device__ __forceinline__ void load_chunk(uint32_t stage_base,
                                           const __half* pAh,
                                           const __half* pAl,
                                           const __half* pB,
                                           int k0, int tid) {
#pragma unroll
    for (int i = 0; i < 4; i++) {
        int id = tid + i * 128;          // 0..511
        int r = id >> 2;
        int c = id & 3;
        uint32_t o = swz(r, c);
        const size_t s = (size_t)r * DIMK + k0 + c * 8;
        cp16(stage_base + o,              pAh + s);
        cp16(stage_base + TILE_B + o,     pAl + s);
        cp16(stage_base + 2 * TILE_B + o, pB  + s);
    }
}

__global__ void __launch_bounds__(128, 2) gemm_mma_kernel(
    const __half* __restrict__ Ahi, const __half* __restrict__ Alo,
    size_t a_estride,
    const __half* __restrict__ Bw,
    const float* __restrict__ bias, int mode,
    __half* __restrict__ Ohi, __half* __restrict__ Olo,
    float* __restrict__ Of)
{
    extern __shared__ char smem[];
    const int tid  = threadIdx.x;
    const int wid  = tid >> 5;
    const int lane = tid & 31;
    const int cb = blockIdx.x;
    const int rb = blockIdx.y;
    const int e  = blockIdx.z;
    const int wm = (wid >> 1) * 64;
    const int wn = (wid & 1) * 64;

    const uint32_t sbase = (uint32_t)__cvta_generic_to_shared(smem);

    const __half* pAh = Ahi + (size_t)e * a_estride + (size_t)rb * 128 * DIMK;
    const __half* pAl = Alo + (size_t)e * a_estride + (size_t)rb * 128 * DIMK;
    const __half* pB  = Bw + ((size_t)e * DIMK + (size_t)cb * 128) * DIMK;

    float acc[4][8][4];
#pragma unroll
    for (int i = 0; i < 4; i++)
#pragma unroll
        for (int j = 0; j < 8; j++)
#pragma unroll
            for (int k = 0; k < 4; k++) acc[i][j][k] = 0.f;

#pragma unroll
    for (int s = 0; s < STAGES - 1; s++) {
        load_chunk(sbase + s * STAGE_B, pAh, pAl, pB, s * 32, tid);
        asm volatile("cp.async.commit_group;" ::: "memory");
    }

    const int jA = lane >> 3;
    const int rA_base = ((jA & 1) << 3) + (lane & 7);
    const int cA_base = jA >> 1;
    const int jB = lane >> 3;
    const int rB_base = ((jB >> 1) << 3) + (lane & 7);
    const int cB_base = jB & 1;

    for (int c = 0; c < CHUNKS; c++) {
        const int pf = c + STAGES - 1;
        if (pf < CHUNKS) {
            asm volatile("cp.async.wait_group %0;" :: "n"(STAGES - 2) : "memory");
        } else {
            asm volatile("cp.async.wait_group 0;" ::: "memory");
        }
        __syncthreads();
        if (pf < CHUNKS) {
            load_chunk(sbase + (pf % STAGES) * STAGE_B, pAh, pAl, pB, pf * 32, tid);
            asm volatile("cp.async.commit_group;" ::: "memory");
        }

        const uint32_t ah_b = sbase + (c % STAGES) * STAGE_B;
        const uint32_t al_b = ah_b + TILE_B;
        const uint32_t b_b  = ah_b + 2 * TILE_B;

#pragma unroll
        for (int ks = 0; ks < 2; ks++) {
            const int kc0 = ks * 2;
            uint32_t bw[8][2];
#pragma unroll
            for (int q = 0; q < 4; q++) {
                int rB = wn + q * 16 + rB_base;
                int cB = kc0 + cB_base;
                uint32_t o = swz(rB, cB);
                uint32_t t[4];
                ldsm_x4(t, b_b + o);
                bw[2 * q][0] = t[0]; bw[2 * q][1] = t[1];
                bw[2 * q + 1][0] = t[2]; bw[2 * q + 1][1] = t[3];
            }
#pragma unroll
            for (int mf = 0; mf < 4; mf++) {
                int rA = wm + mf * 16 + rA_base;
                int cA = kc0 + cA_base;
                uint32_t o = swz(rA, cA);
                uint32_t ah[4], al[4];
                ldsm_x4(ah, ah_b + o);
                ldsm_x4(al, al_b + o);
#pragma unroll
                for (int nf = 0; nf < 8; nf++) {
                    mma_f16(acc[mf][nf], ah, bw[nf]);
                    mma_f16(acc[mf][nf], al, bw[nf]);
                }
            }
        }
    }

    // --------------------------- epilogue ---------------------------
    const float* bias_e = bias + (size_t)e * DIMK;
#pragma unroll
    for (int mf = 0; mf < 4; mf++) {
#pragma unroll
        for (int nf = 0; nf < 8; nf++) {
#pragma unroll
            for (int h = 0; h < 2; h++) {
                int row = rb * 128 + wm + mf * 16 + (lane >> 2) + h * 8;
                int col = cb * 128 + wn + nf * 8 + ((lane & 3) << 1);
                float v0 = acc[mf][nf][2 * h]     + bias_e[col];
                float v1 = acc[mf][nf][2 * h + 1] + bias_e[col + 1];
                size_t o = (size_t)e * ((size_t)B_ROWS * DIMK)
                         + (size_t)row * DIMK + col;
                if (mode) {
                    v0 = 0.5f * v0 * (1.0f + erff(v0 * 0.70710678118654752f));
                    v1 = 0.5f * v1 * (1.0f + erff(v1 * 0.70710678118654752f));
                    __half h0 = __float2half_rn(v0);
                    __half h1 = __float2half_rn(v1);
                    __half2 ph; ph.x = h0; ph.y = h1;
                    __half2 pl;
                    pl.x = __float2half_rn(v0 - __half2float(h0));
                    pl.y = __float2half_rn(v1 - __half2float(h1));
                    *(__half2*)(Ohi + o) = ph;
                    *(__half2*)(Olo + o) = pl;
                } else {
                    float2 v; v.x = v0; v.y = v1;
                    *(float2*)(Of + o) = v;
                }
            }
        }
    }
}

// ---------------------------------------------------------------------------
// LayerNorm + combine: warp-per-expert, shfl reductions, one barrier.
// ---------------------------------------------------------------------------
__global__ void __launch_bounds__(256) ln_combine_kernel(
    const float* __restrict__ gamma, const float* __restrict__ beta,
    float* __restrict__ out)
{
    __shared__ float ybuf[N_EXP][DIMK];
    const int b = blockIdx.x;
    const int tid = threadIdx.x;
    const int e = tid >> 5;
    const int lane = tid & 31;

    const float4* y4 = (const float4*)(g_Y + ((size_t)e * B_ROWS + b) * DIMK);
    float4 v[8];
    float s = 0.f;
#pragma unroll
    for (int j = 0; j < 8; j++) {
        v[j] = y4[j * 32 + lane];
        s += v[j].x + v[j].y + v[j].z + v[j].w;
    }
#pragma unroll
    for (int st = 16; st; st >>= 1) s += __shfl_xor_sync(0xffffffffu, s, st);
    const float mu = s * (1.f / DIMK);

    float s2 = 0.f;
#pragma unroll
    for (int j = 0; j < 8; j++) {
        float dx = v[j].x - mu, dy = v[j].y - mu, dz = v[j].z - mu, dw = v[j].w - mu;
        s2 += dx * dx + dy * dy + dz * dz + dw * dw;
    }
#pragma unroll
    for (int st = 16; st; st >>= 1) s2 += __shfl_xor_sync(0xffffffffu, s2, st);
    const float inv = rsqrtf(s2 * (1.f / DIMK) + 1e-5f);
    const float wgt = g_wts[(size_t)b * N_EXP + e];

    const float4* g4 = (const float4*)(gamma + (size_t)e * DIMK);
    const float4* b4 = (const float4*)(beta + (size_t)e * DIMK);
#pragma unroll
    for (int j = 0; j < 8; j++) {
        int c4 = j * 32 + lane;
        float4 gg = g4[c4], bb = b4[c4], r;
        r.x = wgt * ((v[j].x - mu) * inv * gg.x + bb.x);
        r.y = wgt * ((v[j].y - mu) * inv * gg.y + bb.y);
        r.z = wgt * ((v[j].z - mu) * inv * gg.z + bb.z);
        r.w = wgt * ((v[j].w - mu) * inv * gg.w + bb.w);
        *(float4*)&ybuf[e][c4 * 4] = r;
    }
    __syncthreads();

    float4 a = *(float4*)&ybuf[0][tid * 4];
#pragma unroll
    for (int ee = 1; ee < N_EXP; ee++) {
        float4 u = *(float4*)&ybuf[ee][tid * 4];
        a.x += u.x; a.y += u.y; a.z += u.z; a.w += u.w;
    }
    *(float4*)(out + (size_t)b * DIMK + tid * 4) = a;
}

// ---------------------------------------------------------------------------
// Host launch
// ---------------------------------------------------------------------------
extern "C" void kernel_launch(void* const* d_in, const int* in_sizes, int n_in,
                              void* d_out, int out_size)
{
    const float* z_s   = (const float*)d_in[0];
    const float* z_e   = (const float*)d_in[1];
    const float* rw    = (const float*)d_in[2];
    const float* rb    = (const float*)d_in[3];
    const float* w1    = (const float*)d_in[4];
    const float* b1    = (const float*)d_in[5];
    const float* w2    = (const float*)d_in[6];
    const float* b2    = (const float*)d_in[7];
    const float* gamma = (const float*)d_in[8];
    const float* beta  = (const float*)d_in[9];
    float* out = (float*)d_out;

    __half *comb_hi, *comb_lo, *w1t, *w2t, *H_hi, *H_lo;
    float *Y;
    cudaGetSymbolAddress((void**)&comb_hi, g_comb_hi);
    cudaGetSymbolAddress((void**)&comb_lo, g_comb_lo);
    cudaGetSymbolAddress((void**)&w1t, g_w1t);
    cudaGetSymbolAddress((void**)&w2t, g_w2t);
    cudaGetSymbolAddress((void**)&H_hi, g_H_hi);
    cudaGetSymbolAddress((void**)&H_lo, g_H_lo);
    cudaGetSymbolAddress((void**)&Y, g_Y);

    cudaFuncSetAttribute(gemm_mma_kernel,
                         cudaFuncAttributeMaxDynamicSharedMemorySize, SMEM_BYTES);

    {
        size_t total = (size_t)B_ROWS * DIMK;
        split_comb_kernel<<<(int)((total + 255) / 256), 256>>>(z_s, z_e);
    }
    {
        dim3 tg(16, 16, 8);
        split_wT_kernel<<<tg, 256>>>(w1, w1t);
        split_wT_kernel<<<tg, 256>>>(w2, w2t);
    }
    router_kernel<<<B_ROWS / 32, 256>>>(z_s, z_e, rw, rb);

    dim3 grid(8, 128, 8);
    gemm_mma_kernel<<<grid, 128, SMEM_BYTES>>>(
        comb_hi, comb_lo, (size_t)0,
        w1t, b1, 1,
        H_hi, H_lo, nullptr);
    gemm_mma_kernel<<<grid, 128, SMEM_BYTES>>>(
        H_hi, H_lo, (size_t)B_ROWS * DIMK,
        w2t, b2, 0,
        nullptr, nullptr, Y);

    ln_combine_kernel<<<B_ROWS, 256>>>(gamma, beta, out);
}

// round 9
// speedup vs baseline: 8.6553x; 1.6851x over previous
#include <cuda_runtime.h>
#include <cuda_fp16.h>
#include <math.h>
#include <stdint.h>

#define B_ROWS 16384
#define DIMK   1024
#define N_EXP  8

// ---------------------------------------------------------------------------
// Static device scratch (no allocations allowed)
// ---------------------------------------------------------------------------
__device__ __half g_comb[(size_t)B_ROWS * DIMK];          // fp16 [m][k]
__device__ __half g_w1t[(size_t)N_EXP * DIMK * DIMK];     // [e][n][k] fp16
__device__ __half g_w2t[(size_t)N_EXP * DIMK * DIMK];
__device__ __half g_H[(size_t)N_EXP * B_ROWS * DIMK];     // [e][m][k] fp16
__device__ float  g_Y[(size_t)N_EXP * B_ROWS * DIMK];     // [e][m][n]
__device__ float  g_wts[(size_t)B_ROWS * N_EXP];

// ---------------------------------------------------------------------------
// helpers (sm_80-level PTX only)
// ---------------------------------------------------------------------------
__device__ __forceinline__ void cp16(uint32_t dst, const void* src) {
    asm volatile("cp.async.cg.shared.global [%0], [%1], 16;"
                 :: "r"(dst), "l"(__cvta_generic_to_global(src)) : "memory");
}
__device__ __forceinline__ void ldsm_x4(uint32_t* r, uint32_t addr) {
    asm volatile("ldmatrix.sync.aligned.m8n8.x4.shared.b16 {%0,%1,%2,%3}, [%4];"
                 : "=r"(r[0]), "=r"(r[1]), "=r"(r[2]), "=r"(r[3]) : "r"(addr));
}
__device__ __forceinline__ void mma_f16(float* d, const uint32_t* a, const uint32_t* b) {
    asm volatile("mma.sync.aligned.m16n8k16.row.col.f32.f16.f16.f32 "
                 "{%0,%1,%2,%3}, {%4,%5,%6,%7}, {%8,%9}, {%0,%1,%2,%3};"
                 : "+f"(d[0]), "+f"(d[1]), "+f"(d[2]), "+f"(d[3])
                 : "r"(a[0]), "r"(a[1]), "r"(a[2]), "r"(a[3]), "r"(b[0]), "r"(b[1]));
}
// swizzled byte offset within a [128 rows x 32 fp16] tile (64B rows, 4x16B chunks)
__device__ __forceinline__ uint32_t swz(int r, int c) {
    return (uint32_t)(r * 64 + ((c ^ ((r >> 1) & 3)) << 4));
}

// ---------------------------------------------------------------------------
// Input convert / weight transpose kernels
// ---------------------------------------------------------------------------
__global__ void conv_comb_kernel(const float* __restrict__ zs,
                                 const float* __restrict__ ze) {
    size_t g = (size_t)blockIdx.x * blockDim.x + threadIdx.x;
    if (g >= (size_t)B_ROWS * DIMK) return;
    size_t b = g >> 10; int i = (int)(g & 1023);
    float v = (i < 512) ? zs[(b << 9) + i] : ze[(b << 9) + i - 512];
    g_comb[g] = __float2half_rn(v);
}

// w: [e][k][n] fp32 -> out: [e][n][k] fp16; smem-tiled 64x64 transpose
// grid (16, 16, 8), block 256
__global__ void __launch_bounds__(256) split_wT_kernel(
    const float* __restrict__ w, __half* __restrict__ t)
{
    __shared__ float s[64][65];
    const int tid = threadIdx.x;
    const int tk = blockIdx.y * 64, tn = blockIdx.x * 64;
    const size_t eo = (size_t)blockIdx.z << 20;

#pragma unroll
    for (int i = 0; i < 16; i++) {
        int idx = tid + i * 256;
        int kk = idx >> 6, nn = idx & 63;
        s[kk][nn] = w[eo + (size_t)(tk + kk) * DIMK + tn + nn];
    }
    __syncthreads();
#pragma unroll
    for (int i = 0; i < 16; i++) {
        int idx = tid + i * 256;
        int nn = idx >> 6, kk = idx & 63;
        t[eo + (size_t)(tn + nn) * DIMK + tk + kk] = __float2half_rn(s[kk][nn]);
    }
}

// ---------------------------------------------------------------------------
// Router softmax: warp-per-4-rows, smem-transposed weights, shfl reductions
// ---------------------------------------------------------------------------
__global__ void __launch_bounds__(256) router_kernel(
    const float* __restrict__ zs, const float* __restrict__ ze,
    const float* __restrict__ rw, const float* __restrict__ rb)
{
    __shared__ float rws[N_EXP][DIMK];
    __shared__ float rbs[N_EXP];
    const int tid = threadIdx.x, lane = tid & 31, w = tid >> 5;

    for (int i = tid; i < N_EXP * DIMK; i += 256) {
        int k = i >> 3, e = i & 7;
        rws[e][k] = rw[i];
    }
    if (tid < N_EXP) rbs[tid] = rb[tid];
    __syncthreads();

    const int row0 = blockIdx.x * 32 + w * 4;
#pragma unroll 1
    for (int rr = 0; rr < 4; rr++) {
        const int b = row0 + rr;
        float acc[N_EXP];
#pragma unroll
        for (int e = 0; e < N_EXP; e++) acc[e] = 0.f;
#pragma unroll
        for (int j = 0; j < 32; j++) {
            int k = j * 32 + lane;
            float xv = (k < 512) ? zs[(size_t)b * 512 + k]
                                 : ze[(size_t)b * 512 + k - 512];
#pragma unroll
            for (int e = 0; e < N_EXP; e++) acc[e] += xv * rws[e][k];
        }
#pragma unroll
        for (int e = 0; e < N_EXP; e++)
#pragma unroll
            for (int s = 16; s; s >>= 1)
                acc[e] += __shfl_xor_sync(0xffffffffu, acc[e], s);
        if (lane == 0) {
            float mx = -1e30f;
#pragma unroll
            for (int e = 0; e < N_EXP; e++) { acc[e] += rbs[e]; mx = fmaxf(mx, acc[e]); }
            float sum = 0.f;
#pragma unroll
            for (int e = 0; e < N_EXP; e++) { acc[e] = expf(acc[e] - mx); sum += acc[e]; }
            float inv = 1.f / sum;
#pragma unroll
            for (int e = 0; e < N_EXP; e++) g_wts[(size_t)b * N_EXP + e] = acc[e] * inv;
        }
    }
}

// ---------------------------------------------------------------------------
// fp16 mma.sync GEMM, single term (A @ B^T), single-barrier pipeline.
// CTA 128x128, BK=32, 6 stages, 4 warps (2x2), warp tile 64x64.
// ---------------------------------------------------------------------------
#define TILE_B   8192
#define STAGE_B  (2 * TILE_B)            // A, B
#define STAGES   6
#define SMEM_BYTES (STAGES * STAGE_B)    // 96 KB
#define CHUNKS   (DIMK / 32)             // 32

__device__ __forceinline__ void load_chunk(uint32_t stage_base,
                                           const __half* pA,
                                           const __half* pB,
                                           int k0, int tid) {
#pragma unroll
    for (int i = 0; i < 4; i++) {
        int id = tid + i * 128;          // 0..511
        int r = id >> 2;
        int c = id & 3;
        uint32_t o = swz(r, c);
        const size_t s = (size_t)r * DIMK + k0 + c * 8;
        cp16(stage_base + o,          pA + s);
        cp16(stage_base + TILE_B + o, pB + s);
    }
}

__global__ void __launch_bounds__(128, 2) gemm_mma_kernel(
    const __half* __restrict__ A, size_t a_estride,
    const __half* __restrict__ Bw,
    const float* __restrict__ bias, int mode,
    __half* __restrict__ Oh, float* __restrict__ Of)
{
    extern __shared__ char smem[];
    const int tid  = threadIdx.x;
    const int wid  = tid >> 5;
    const int lane = tid & 31;
    const int cb = blockIdx.x;
    const int rb = blockIdx.y;
    const int e  = blockIdx.z;
    const int wm = (wid >> 1) * 64;
    const int wn = (wid & 1) * 64;

    const uint32_t sbase = (uint32_t)__cvta_generic_to_shared(smem);

    const __half* pA = A + (size_t)e * a_estride + (size_t)rb * 128 * DIMK;
    const __half* pB = Bw + ((size_t)e * DIMK + (size_t)cb * 128) * DIMK;

    float acc[4][8][4];
#pragma unroll
    for (int i = 0; i < 4; i++)
#pragma unroll
        for (int j = 0; j < 8; j++)
#pragma unroll
            for (int k = 0; k < 4; k++) acc[i][j][k] = 0.f;

#pragma unroll
    for (int s = 0; s < STAGES - 1; s++) {
        load_chunk(sbase + s * STAGE_B, pA, pB, s * 32, tid);
        asm volatile("cp.async.commit_group;" ::: "memory");
    }

    const int jA = lane >> 3;
    const int rA_base = ((jA & 1) << 3) + (lane & 7);
    const int cA_base = jA >> 1;
    const int jB = lane >> 3;
    const int rB_base = ((jB >> 1) << 3) + (lane & 7);
    const int cB_base = jB & 1;

    for (int c = 0; c < CHUNKS; c++) {
        const int pf = c + STAGES - 1;
        if (pf < CHUNKS) {
            asm volatile("cp.async.wait_group %0;" :: "n"(STAGES - 2) : "memory");
        } else {
            asm volatile("cp.async.wait_group 0;" ::: "memory");
        }
        __syncthreads();
        if (pf < CHUNKS) {
            load_chunk(sbase + (pf % STAGES) * STAGE_B, pA, pB, pf * 32, tid);
            asm volatile("cp.async.commit_group;" ::: "memory");
        }

        const uint32_t a_b = sbase + (c % STAGES) * STAGE_B;
        const uint32_t b_b = a_b + TILE_B;

#pragma unroll
        for (int ks = 0; ks < 2; ks++) {
            const int kc0 = ks * 2;
            uint32_t bw[8][2];
#pragma unroll
            for (int q = 0; q < 4; q++) {
                int rB = wn + q * 16 + rB_base;
                int cB = kc0 + cB_base;
                uint32_t o = swz(rB, cB);
                uint32_t t[4];
                ldsm_x4(t, b_b + o);
                bw[2 * q][0] = t[0]; bw[2 * q][1] = t[1];
                bw[2 * q + 1][0] = t[2]; bw[2 * q + 1][1] = t[3];
            }
#pragma unroll
            for (int mf = 0; mf < 4; mf++) {
                int rA = wm + mf * 16 + rA_base;
                int cA = kc0 + cA_base;
                uint32_t o = swz(rA, cA);
                uint32_t av[4];
                ldsm_x4(av, a_b + o);
#pragma unroll
                for (int nf = 0; nf < 8; nf++)
                    mma_f16(acc[mf][nf], av, bw[nf]);
            }
        }
    }

    // --------------------------- epilogue ---------------------------
    const float* bias_e = bias + (size_t)e * DIMK;
#pragma unroll
    for (int mf = 0; mf < 4; mf++) {
#pragma unroll
        for (int nf = 0; nf < 8; nf++) {
#pragma unroll
            for (int h = 0; h < 2; h++) {
                int row = rb * 128 + wm + mf * 16 + (lane >> 2) + h * 8;
                int col = cb * 128 + wn + nf * 8 + ((lane & 3) << 1);
                float v0 = acc[mf][nf][2 * h]     + bias_e[col];
                float v1 = acc[mf][nf][2 * h + 1] + bias_e[col + 1];
                size_t o = (size_t)e * ((size_t)B_ROWS * DIMK)
                         + (size_t)row * DIMK + col;
                if (mode) {
                    v0 = 0.5f * v0 * (1.0f + erff(v0 * 0.70710678118654752f));
                    v1 = 0.5f * v1 * (1.0f + erff(v1 * 0.70710678118654752f));
                    __half2 ph;
                    ph.x = __float2half_rn(v0);
                    ph.y = __float2half_rn(v1);
                    *(__half2*)(Oh + o) = ph;
                } else {
                    float2 v; v.x = v0; v.y = v1;
                    *(float2*)(Of + o) = v;
                }
            }
        }
    }
}

// ---------------------------------------------------------------------------
// LayerNorm + combine: warp-per-expert, shfl reductions, one barrier.
// ---------------------------------------------------------------------------
__global__ void __launch_bounds__(256) ln_combine_kernel(
    const float* __restrict__ gamma, const float* __restrict__ beta,
    float* __restrict__ out)
{
    __shared__ float ybuf[N_EXP][DIMK];
    const int b = blockIdx.x;
    const int tid = threadIdx.x;
    const int e = tid >> 5;
    const int lane = tid & 31;

    const float4* y4 = (const float4*)(g_Y + ((size_t)e * B_ROWS + b) * DIMK);
    float4 v[8];
    float s = 0.f;
#pragma unroll
    for (int j = 0; j < 8; j++) {
        v[j] = y4[j * 32 + lane];
        s += v[j].x + v[j].y + v[j].z + v[j].w;
    }
#pragma unroll
    for (int st = 16; st; st >>= 1) s += __shfl_xor_sync(0xffffffffu, s, st);
    const float mu = s * (1.f / DIMK);

    float s2 = 0.f;
#pragma unroll
    for (int j = 0; j < 8; j++) {
        float dx = v[j].x - mu, dy = v[j].y - mu, dz = v[j].z - mu, dw = v[j].w - mu;
        s2 += dx * dx + dy * dy + dz * dz + dw * dw;
    }
#pragma unroll
    for (int st = 16; st; st >>= 1) s2 += __shfl_xor_sync(0xffffffffu, s2, st);
    const float inv = rsqrtf(s2 * (1.f / DIMK) + 1e-5f);
    const float wgt = g_wts[(size_t)b * N_EXP + e];

    const float4* g4 = (const float4*)(gamma + (size_t)e * DIMK);
    const float4* b4 = (const float4*)(beta + (size_t)e * DIMK);
#pragma unroll
    for (int j = 0; j < 8; j++) {
        int c4 = j * 32 + lane;
        float4 gg = g4[c4], bb = b4[c4], r;
        r.x = wgt * ((v[j].x - mu) * inv * gg.x + bb.x);
        r.y = wgt * ((v[j].y - mu) * inv * gg.y + bb.y);
        r.z = wgt * ((v[j].z - mu) * inv * gg.z + bb.z);
        r.w = wgt * ((v[j].w - mu) * inv * gg.w + bb.w);
        *(float4*)&ybuf[e][c4 * 4] = r;
    }
    __syncthreads();

    float4 a = *(float4*)&ybuf[0][tid * 4];
#pragma unroll
    for (int ee = 1; ee < N_EXP; ee++) {
        float4 u = *(float4*)&ybuf[ee][tid * 4];
        a.x += u.x; a.y += u.y; a.z += u.z; a.w += u.w;
    }
    *(float4*)(out + (size_t)b * DIMK + tid * 4) = a;
}

// ---------------------------------------------------------------------------
// Host launch
// ---------------------------------------------------------------------------
extern "C" void kernel_launch(void* const* d_in, const int* in_sizes, int n_in,
                              void* d_out, int out_size)
{
    const float* z_s   = (const float*)d_in[0];
    const float* z_e   = (const float*)d_in[1];
    const float* rw    = (const float*)d_in[2];
    const float* rb    = (const float*)d_in[3];
    const float* w1    = (const float*)d_in[4];
    const float* b1    = (const float*)d_in[5];
    const float* w2    = (const float*)d_in[6];
    const float* b2    = (const float*)d_in[7];
    const float* gamma = (const float*)d_in[8];
    const float* beta  = (const float*)d_in[9];
    float* out = (float*)d_out;

    __half *comb, *w1t, *w2t, *H;
    float *Y;
    cudaGetSymbolAddress((void**)&comb, g_comb);
    cudaGetSymbolAddress((void**)&w1t, g_w1t);
    cudaGetSymbolAddress((void**)&w2t, g_w2t);
    cudaGetSymbolAddress((void**)&H, g_H);
    cudaGetSymbolAddress((void**)&Y, g_Y);

    cudaFuncSetAttribute(gemm_mma_kernel,
                         cudaFuncAttributeMaxDynamicSharedMemorySize, SMEM_BYTES);

    {
        size_t total = (size_t)B_ROWS * DIMK;
        conv_comb_kernel<<<(int)((total + 255) / 256), 256>>>(z_s, z_e);
    }
    {
        dim3 tg(16, 16, 8);
        split_wT_kernel<<<tg, 256>>>(w1, w1t);
        split_wT_kernel<<<tg, 256>>>(w2, w2t);
    }
    router_kernel<<<B_ROWS / 32, 256>>>(z_s, z_e, rw, rb);

    dim3 grid(8, 128, 8);
    // GEMM1: H = fp16(gelu(comb @ w1 + b1))
    gemm_mma_kernel<<<grid, 128, SMEM_BYTES>>>(
        comb, (size_t)0, w1t, b1, 1, H, nullptr);
    // GEMM2: Y = H @ w2 + b2 (fp32)
    gemm_mma_kernel<<<grid, 128, SMEM_BYTES>>>(
        H, (size_t)B_ROWS * DIMK, w2t, b2, 0, nullptr, Y);

    ln_combine_kernel<<<B_ROWS, 256>>>(gamma, beta, out);
}

// round 11
// speedup vs baseline: 8.6951x; 1.0046x over previous
#include <cuda_runtime.h>
#include <cuda_fp16.h>
#include <math.h>
#include <stdint.h>

#define B_ROWS 16384
#define DIMK   1024
#define N_EXP  8

// ---------------------------------------------------------------------------
// Static device scratch (no allocations allowed)
// ---------------------------------------------------------------------------
__device__ __half g_comb[(size_t)B_ROWS * DIMK];          // fp16 [m][k]
__device__ __half g_w1t[(size_t)N_EXP * DIMK * DIMK];     // [e][n][k] fp16
__device__ __half g_w2t[(size_t)N_EXP * DIMK * DIMK];
__device__ __half g_H[(size_t)N_EXP * B_ROWS * DIMK];     // [e][m][k] fp16
__device__ __half g_Yh[(size_t)N_EXP * B_ROWS * DIMK];    // [e][m][n] fp16
__device__ float  g_wts[(size_t)B_ROWS * N_EXP];

// ---------------------------------------------------------------------------
// helpers (sm_80-level PTX only)
// ---------------------------------------------------------------------------
__device__ __forceinline__ void cp16(uint32_t dst, const void* src) {
    asm volatile("cp.async.cg.shared.global [%0], [%1], 16;"
                 :: "r"(dst), "l"(__cvta_generic_to_global(src)) : "memory");
}
__device__ __forceinline__ void ldsm_x4(uint32_t* r, uint32_t addr) {
    asm volatile("ldmatrix.sync.aligned.m8n8.x4.shared.b16 {%0,%1,%2,%3}, [%4];"
                 : "=r"(r[0]), "=r"(r[1]), "=r"(r[2]), "=r"(r[3]) : "r"(addr));
}
__device__ __forceinline__ void mma_f16(float* d, const uint32_t* a, const uint32_t* b) {
    asm volatile("mma.sync.aligned.m16n8k16.row.col.f32.f16.f16.f32 "
                 "{%0,%1,%2,%3}, {%4,%5,%6,%7}, {%8,%9}, {%0,%1,%2,%3};"
                 : "+f"(d[0]), "+f"(d[1]), "+f"(d[2]), "+f"(d[3])
                 : "r"(a[0]), "r"(a[1]), "r"(a[2]), "r"(a[3]), "r"(b[0]), "r"(b[1]));
}
// swizzled byte offset within a [128 rows x 32 fp16] tile (64B rows, 4x16B chunks)
__device__ __forceinline__ uint32_t swz(int r, int c) {
    return (uint32_t)(r * 64 + ((c ^ ((r >> 1) & 3)) << 4));
}

// ---------------------------------------------------------------------------
// Input convert / weight transpose kernels
// ---------------------------------------------------------------------------
__global__ void conv_comb_kernel(const float* __restrict__ zs,
                                 const float* __restrict__ ze) {
    size_t g = (size_t)blockIdx.x * blockDim.x + threadIdx.x;
    if (g >= (size_t)B_ROWS * DIMK) return;
    size_t b = g >> 10; int i = (int)(g & 1023);
    float v = (i < 512) ? zs[(b << 9) + i] : ze[(b << 9) + i - 512];
    g_comb[g] = __float2half_rn(v);
}

// w: [e][k][n] fp32 -> out: [e][n][k] fp16; smem-tiled 64x64 transpose
// grid (16, 16, 8), block 256
__global__ void __launch_bounds__(256) split_wT_kernel(
    const float* __restrict__ w, __half* __restrict__ t)
{
    __shared__ float s[64][65];
    const int tid = threadIdx.x;
    const int tk = blockIdx.y * 64, tn = blockIdx.x * 64;
    const size_t eo = (size_t)blockIdx.z << 20;

#pragma unroll
    for (int i = 0; i < 16; i++) {
        int idx = tid + i * 256;
        int kk = idx >> 6, nn = idx & 63;
        s[kk][nn] = w[eo + (size_t)(tk + kk) * DIMK + tn + nn];
    }
    __syncthreads();
#pragma unroll
    for (int i = 0; i < 16; i++) {
        int idx = tid + i * 256;
        int nn = idx >> 6, kk = idx & 63;
        t[eo + (size_t)(tn + nn) * DIMK + tk + kk] = __float2half_rn(s[kk][nn]);
    }
}

// ---------------------------------------------------------------------------
// Router softmax: ONE row per warp (was 4 -> regs 255, occ 12%).
// grid = B_ROWS/8, block = 256 (8 warps)
// ---------------------------------------------------------------------------
__global__ void __launch_bounds__(256) router_kernel(
    const float* __restrict__ zs, const float* __restrict__ ze,
    const float* __restrict__ rw, const float* __restrict__ rb)
{
    __shared__ float rws[N_EXP][DIMK];
    __shared__ float rbs[N_EXP];
    const int tid = threadIdx.x, lane = tid & 31, w = tid >> 5;

    for (int i = tid; i < N_EXP * DIMK; i += 256) {
        int k = i >> 3, e = i & 7;
        rws[e][k] = rw[i];
    }
    if (tid < N_EXP) rbs[tid] = rb[tid];
    __syncthreads();

    const int b = blockIdx.x * 8 + w;
    float acc[N_EXP];
#pragma unroll
    for (int e = 0; e < N_EXP; e++) acc[e] = 0.f;
#pragma unroll
    for (int j = 0; j < 32; j++) {
        int k = j * 32 + lane;
        float xv = (k < 512) ? zs[(size_t)b * 512 + k]
                             : ze[(size_t)b * 512 + k - 512];
#pragma unroll
        for (int e = 0; e < N_EXP; e++) acc[e] += xv * rws[e][k];
    }
#pragma unroll
    for (int e = 0; e < N_EXP; e++)
#pragma unroll
        for (int s = 16; s; s >>= 1)
            acc[e] += __shfl_xor_sync(0xffffffffu, acc[e], s);
    if (lane == 0) {
        float mx = -1e30f;
#pragma unroll
        for (int e = 0; e < N_EXP; e++) { acc[e] += rbs[e]; mx = fmaxf(mx, acc[e]); }
        float sum = 0.f;
#pragma unroll
        for (int e = 0; e < N_EXP; e++) { acc[e] = expf(acc[e] - mx); sum += acc[e]; }
        float inv = 1.f / sum;
#pragma unroll
        for (int e = 0; e < N_EXP; e++) g_wts[(size_t)b * N_EXP + e] = acc[e] * inv;
    }
}

// ---------------------------------------------------------------------------
// fp16 mma.sync GEMM, single term (A @ B^T), single-barrier pipeline.
// CTA 128x128, BK=32, 6 stages, 4 warps (2x2), warp tile 64x64.
// mode 1: Oh = fp16(gelu(D+bias));  mode 0: Oh = fp16(D+bias)
// ---------------------------------------------------------------------------
#define TILE_B   8192
#define STAGE_B  (2 * TILE_B)            // A, B
#define STAGES   6
#define SMEM_BYTES (STAGES * STAGE_B)    // 96 KB
#define CHUNKS   (DIMK / 32)             // 32

__device__ __forceinline__ void load_chunk(uint32_t stage_base,
                                           const __half* pA,
                                           const __half* pB,
                                           int k0, int tid) {
#pragma unroll
    for (int i = 0; i < 4; i++) {
        int id = tid + i * 128;          // 0..511
        int r = id >> 2;
        int c = id & 3;
        uint32_t o = swz(r, c);
        const size_t s = (size_t)r * DIMK + k0 + c * 8;
        cp16(stage_base + o,          pA + s);
        cp16(stage_base + TILE_B + o, pB + s);
    }
}

__global__ void __launch_bounds__(128, 2) gemm_mma_kernel(
    const __half* __restrict__ A, size_t a_estride,
    const __half* __restrict__ Bw,
    const float* __restrict__ bias, int mode,
    __half* __restrict__ Oh)
{
    extern __shared__ char smem[];
    const int tid  = threadIdx.x;
    const int wid  = tid >> 5;
    const int lane = tid & 31;
    const int cb = blockIdx.x;
    const int rb = blockIdx.y;
    const int e  = blockIdx.z;
    const int wm = (wid >> 1) * 64;
    const int wn = (wid & 1) * 64;

    const uint32_t sbase = (uint32_t)__cvta_generic_to_shared(smem);

    const __half* pA = A + (size_t)e * a_estride + (size_t)rb * 128 * DIMK;
    const __half* pB = Bw + ((size_t)e * DIMK + (size_t)cb * 128) * DIMK;

    float acc[4][8][4];
#pragma unroll
    for (int i = 0; i < 4; i++)
#pragma unroll
        for (int j = 0; j < 8; j++)
#pragma unroll
            for (int k = 0; k < 4; k++) acc[i][j][k] = 0.f;

#pragma unroll
    for (int s = 0; s < STAGES - 1; s++) {
        load_chunk(sbase + s * STAGE_B, pA, pB, s * 32, tid);
        asm volatile("cp.async.commit_group;" ::: "memory");
    }

    const int jA = lane >> 3;
    const int rA_base = ((jA & 1) << 3) + (lane & 7);
    const int cA_base = jA >> 1;
    const int jB = lane >> 3;
    const int rB_base = ((jB >> 1) << 3) + (lane & 7);
    const int cB_base = jB & 1;

    for (int c = 0; c < CHUNKS; c++) {
        const int pf = c + STAGES - 1;
        if (pf < CHUNKS) {
            asm volatile("cp.async.wait_group %0;" :: "n"(STAGES - 2) : "memory");
        } else {
            asm volatile("cp.async.wait_group 0;" ::: "memory");
        }
        __syncthreads();
        if (pf < CHUNKS) {
            load_chunk(sbase + (pf % STAGES) * STAGE_B, pA, pB, pf * 32, tid);
            asm volatile("cp.async.commit_group;" ::: "memory");
        }

        const uint32_t a_b = sbase + (c % STAGES) * STAGE_B;
        const uint32_t b_b = a_b + TILE_B;

#pragma unroll
        for (int ks = 0; ks < 2; ks++) {
            const int kc0 = ks * 2;
            uint32_t bw[8][2];
#pragma unroll
            for (int q = 0; q < 4; q++) {
                int rB = wn + q * 16 + rB_base;
                int cB = kc0 + cB_base;
                uint32_t o = swz(rB, cB);
                uint32_t t[4];
                ldsm_x4(t, b_b + o);
                bw[2 * q][0] = t[0]; bw[2 * q][1] = t[1];
                bw[2 * q + 1][0] = t[2]; bw[2 * q + 1][1] = t[3];
            }
#pragma unroll
            for (int mf = 0; mf < 4; mf++) {
                int rA = wm + mf * 16 + rA_base;
                int cA = kc0 + cA_base;
                uint32_t o = swz(rA, cA);
                uint32_t av[4];
                ldsm_x4(av, a_b + o);
#pragma unroll
                for (int nf = 0; nf < 8; nf++)
                    mma_f16(acc[mf][nf], av, bw[nf]);
            }
        }
    }

    // --------------------------- epilogue ---------------------------
    const float* bias_e = bias + (size_t)e * DIMK;
#pragma unroll
    for (int mf = 0; mf < 4; mf++) {
#pragma unroll
        for (int nf = 0; nf < 8; nf++) {
#pragma unroll
            for (int h = 0; h < 2; h++) {
                int row = rb * 128 + wm + mf * 16 + (lane >> 2) + h * 8;
                int col = cb * 128 + wn + nf * 8 + ((lane & 3) << 1);
                float v0 = acc[mf][nf][2 * h]     + bias_e[col];
                float v1 = acc[mf][nf][2 * h + 1] + bias_e[col + 1];
                size_t o = (size_t)e * ((size_t)B_ROWS * DIMK)
                         + (size_t)row * DIMK + col;
                if (mode) {
                    v0 = 0.5f * v0 * (1.0f + erff(v0 * 0.70710678118654752f));
                    v1 = 0.5f * v1 * (1.0f + erff(v1 * 0.70710678118654752f));
                }
                __half2 ph;
                ph.x = __float2half_rn(v0);
                ph.y = __float2half_rn(v1);
                *(__half2*)(Oh + o) = ph;
            }
        }
    }
}

// ---------------------------------------------------------------------------
// LayerNorm + combine: warp-per-expert, fp16 Y input, shfl reductions.
// grid = B_ROWS, block = 256 (8 warps = 8 experts)
// ---------------------------------------------------------------------------
__global__ void __launch_bounds__(256) ln_combine_kernel(
    const float* __restrict__ gamma, const float* __restrict__ beta,
    float* __restrict__ out)
{
    __shared__ float ybuf[N_EXP][DIMK];
    const int b = blockIdx.x;
    const int tid = threadIdx.x;
    const int e = tid >> 5;
    const int lane = tid & 31;

    // each lane loads 32 halves = 4 x 16B
    const uint4* y4 = (const uint4*)(g_Yh + ((size_t)e * B_ROWS + b) * DIMK);
    float v[32];
    float s = 0.f;
#pragma unroll
    for (int j = 0; j < 4; j++) {
        uint4 raw = y4[j * 32 + lane];
        const uint32_t wds[4] = {raw.x, raw.y, raw.z, raw.w};
#pragma unroll
        for (int q = 0; q < 4; q++) {
            __half2 h2 = *(const __half2*)&wds[q];
            float2 f = __half22float2(h2);
            v[j * 8 + q * 2]     = f.x;
            v[j * 8 + q * 2 + 1] = f.y;
            s += f.x + f.y;
        }
    }
#pragma unroll
    for (int st = 16; st; st >>= 1) s += __shfl_xor_sync(0xffffffffu, s, st);
    const float mu = s * (1.f / DIMK);

    float s2 = 0.f;
#pragma unroll
    for (int i = 0; i < 32; i++) {
        float d = v[i] - mu;
        s2 += d * d;
    }
#pragma unroll
    for (int st = 16; st; st >>= 1) s2 += __shfl_xor_sync(0xffffffffu, s2, st);
    const float inv = rsqrtf(s2 * (1.f / DIMK) + 1e-5f);
    const float wgt = g_wts[(size_t)b * N_EXP + e];

    // lane j covers columns [j*... ]: element v[j*8..] maps to col = (j*32+lane)*8
    const float4* g4 = (const float4*)(gamma + (size_t)e * DIMK);
    const float4* b4 = (const float4*)(beta + (size_t)e * DIMK);
#pragma unroll
    for (int j = 0; j < 4; j++) {
        int base4 = (j * 32 + lane) * 2;     // in units of float4 (4 floats)
#pragma unroll
        for (int hh = 0; hh < 2; hh++) {
            float4 gg = g4[base4 + hh], bb = b4[base4 + hh], r;
            int vi = j * 8 + hh * 4;
            r.x = wgt * ((v[vi]     - mu) * inv * gg.x + bb.x);
            r.y = wgt * ((v[vi + 1] - mu) * inv * gg.y + bb.y);
            r.z = wgt * ((v[vi + 2] - mu) * inv * gg.z + bb.z);
            r.w = wgt * ((v[vi + 3] - mu) * inv * gg.w + bb.w);
            *(float4*)&ybuf[e][(base4 + hh) * 4] = r;
        }
    }
    __syncthreads();

    float4 a = *(float4*)&ybuf[0][tid * 4];
#pragma unroll
    for (int ee = 1; ee < N_EXP; ee++) {
        float4 u = *(float4*)&ybuf[ee][tid * 4];
        a.x += u.x; a.y += u.y; a.z += u.z; a.w += u.w;
    }
    *(float4*)(out + (size_t)b * DIMK + tid * 4) = a;
}

// ---------------------------------------------------------------------------
// Host launch
// ---------------------------------------------------------------------------
extern "C" void kernel_launch(void* const* d_in, const int* in_sizes, int n_in,
                              void* d_out, int out_size)
{
    const float* z_s   = (const float*)d_in[0];
    const float* z_e   = (const float*)d_in[1];
    const float* rw    = (const float*)d_in[2];
    const float* rb    = (const float*)d_in[3];
    const float* w1    = (const float*)d_in[4];
    const float* b1    = (const float*)d_in[5];
    const float* w2    = (const float*)d_in[6];
    const float* b2    = (const float*)d_in[7];
    const float* gamma = (const float*)d_in[8];
    const float* beta  = (const float*)d_in[9];
    float* out = (float*)d_out;

    __half *comb, *w1t, *w2t, *H, *Yh;
    cudaGetSymbolAddress((void**)&comb, g_comb);
    cudaGetSymbolAddress((void**)&w1t, g_w1t);
    cudaGetSymbolAddress((void**)&w2t, g_w2t);
    cudaGetSymbolAddress((void**)&H, g_H);
    cudaGetSymbolAddress((void**)&Yh, g_Yh);

    cudaFuncSetAttribute(gemm_mma_kernel,
                         cudaFuncAttributeMaxDynamicSharedMemorySize, SMEM_BYTES);

    {
        size_t total = (size_t)B_ROWS * DIMK;
        conv_comb_kernel<<<(int)((total + 255) / 256), 256>>>(z_s, z_e);
    }
    {
        dim3 tg(16, 16, 8);
        split_wT_kernel<<<tg, 256>>>(w1, w1t);
        split_wT_kernel<<<tg, 256>>>(w2, w2t);
    }
    router_kernel<<<B_ROWS / 8, 256>>>(z_s, z_e, rw, rb);

    dim3 grid(8, 128, 8);
    // GEMM1: H = fp16(gelu(comb @ w1 + b1))
    gemm_mma_kernel<<<grid, 128, SMEM_BYTES>>>(
        comb, (size_t)0, w1t, b1, 1, H);
    // GEMM2: Yh = fp16(H @ w2 + b2)
    gemm_mma_kernel<<<grid, 128, SMEM_BYTES>>>(
        H, (size_t)B_ROWS * DIMK, w2t, b2, 0, Yh);

    ln_combine_kernel<<<B_ROWS, 256>>>(gamma, beta, out);
}

// round 12
// speedup vs baseline: 9.2045x; 1.0586x over previous
#include <cuda_runtime.h>
#include <cuda_fp16.h>
#include <math.h>
#include <stdint.h>

#define B_ROWS 16384
#define DIMK   1024
#define N_EXP  8

// ---------------------------------------------------------------------------
// Static device scratch (no allocations allowed)
// ---------------------------------------------------------------------------
__device__ __half g_comb[(size_t)B_ROWS * DIMK];          // fp16 [m][k]
__device__ __half g_w1t[(size_t)N_EXP * DIMK * DIMK];     // [e][n][k] fp16
__device__ __half g_w2t[(size_t)N_EXP * DIMK * DIMK];
__device__ __half g_H[(size_t)N_EXP * B_ROWS * DIMK];     // [e][m][k] fp16
__device__ __half g_Yh[(size_t)N_EXP * B_ROWS * DIMK];    // [e][m][n] fp16
__device__ float  g_wts[(size_t)B_ROWS * N_EXP];

// ---------------------------------------------------------------------------
// helpers (sm_80-level PTX only)
// ---------------------------------------------------------------------------
__device__ __forceinline__ void cp16(uint32_t dst, const void* src) {
    asm volatile("cp.async.cg.shared.global [%0], [%1], 16;"
                 :: "r"(dst), "l"(__cvta_generic_to_global(src)) : "memory");
}
__device__ __forceinline__ void ldsm_x4(uint32_t* r, uint32_t addr) {
    asm volatile("ldmatrix.sync.aligned.m8n8.x4.shared.b16 {%0,%1,%2,%3}, [%4];"
                 : "=r"(r[0]), "=r"(r[1]), "=r"(r[2]), "=r"(r[3]) : "r"(addr));
}
__device__ __forceinline__ void mma_f16(float* d, const uint32_t* a, const uint32_t* b) {
    asm volatile("mma.sync.aligned.m16n8k16.row.col.f32.f16.f16.f32 "
                 "{%0,%1,%2,%3}, {%4,%5,%6,%7}, {%8,%9}, {%0,%1,%2,%3};"
                 : "+f"(d[0]), "+f"(d[1]), "+f"(d[2]), "+f"(d[3])
                 : "r"(a[0]), "r"(a[1]), "r"(a[2]), "r"(a[3]), "r"(b[0]), "r"(b[1]));
}
// swizzled byte offset within a [128 rows x 64 fp16] tile (128B rows, 8x16B chunks)
__device__ __forceinline__ uint32_t swz(int r, int c) {
    return (uint32_t)(r * 128 + ((c ^ (r & 7)) << 4));
}

// ---------------------------------------------------------------------------
// Input convert / weight transpose kernels
// ---------------------------------------------------------------------------
__global__ void conv_comb_kernel(const float* __restrict__ zs,
                                 const float* __restrict__ ze) {
    size_t g = (size_t)blockIdx.x * blockDim.x + threadIdx.x;
    if (g >= (size_t)B_ROWS * DIMK) return;
    size_t b = g >> 10; int i = (int)(g & 1023);
    float v = (i < 512) ? zs[(b << 9) + i] : ze[(b << 9) + i - 512];
    g_comb[g] = __float2half_rn(v);
}

// w: [e][k][n] fp32 -> out: [e][n][k] fp16; smem-tiled 64x64 transpose
__global__ void __launch_bounds__(256) split_wT_kernel(
    const float* __restrict__ w, __half* __restrict__ t)
{
    __shared__ float s[64][65];
    const int tid = threadIdx.x;
    const int tk = blockIdx.y * 64, tn = blockIdx.x * 64;
    const size_t eo = (size_t)blockIdx.z << 20;

#pragma unroll
    for (int i = 0; i < 16; i++) {
        int idx = tid + i * 256;
        int kk = idx >> 6, nn = idx & 63;
        s[kk][nn] = w[eo + (size_t)(tk + kk) * DIMK + tn + nn];
    }
    __syncthreads();
#pragma unroll
    for (int i = 0; i < 16; i++) {
        int idx = tid + i * 256;
        int nn = idx >> 6, kk = idx & 63;
        t[eo + (size_t)(tn + nn) * DIMK + tk + kk] = __float2half_rn(s[kk][nn]);
    }
}

// ---------------------------------------------------------------------------
// Router softmax: one row per warp
// ---------------------------------------------------------------------------
__global__ void __launch_bounds__(256) router_kernel(
    const float* __restrict__ zs, const float* __restrict__ ze,
    const float* __restrict__ rw, const float* __restrict__ rb)
{
    __shared__ float rws[N_EXP][DIMK];
    __shared__ float rbs[N_EXP];
    const int tid = threadIdx.x, lane = tid & 31, w = tid >> 5;

    for (int i = tid; i < N_EXP * DIMK; i += 256) {
        int k = i >> 3, e = i & 7;
        rws[e][k] = rw[i];
    }
    if (tid < N_EXP) rbs[tid] = rb[tid];
    __syncthreads();

    const int b = blockIdx.x * 8 + w;
    float acc[N_EXP];
#pragma unroll
    for (int e = 0; e < N_EXP; e++) acc[e] = 0.f;
#pragma unroll
    for (int j = 0; j < 32; j++) {
        int k = j * 32 + lane;
        float xv = (k < 512) ? zs[(size_t)b * 512 + k]
                             : ze[(size_t)b * 512 + k - 512];
#pragma unroll
        for (int e = 0; e < N_EXP; e++) acc[e] += xv * rws[e][k];
    }
#pragma unroll
    for (int e = 0; e < N_EXP; e++)
#pragma unroll
        for (int s = 16; s; s >>= 1)
            acc[e] += __shfl_xor_sync(0xffffffffu, acc[e], s);
    if (lane == 0) {
        float mx = -1e30f;
#pragma unroll
        for (int e = 0; e < N_EXP; e++) { acc[e] += rbs[e]; mx = fmaxf(mx, acc[e]); }
        float sum = 0.f;
#pragma unroll
        for (int e = 0; e < N_EXP; e++) { acc[e] = expf(acc[e] - mx); sum += acc[e]; }
        float inv = 1.f / sum;
#pragma unroll
        for (int e = 0; e < N_EXP; e++) g_wts[(size_t)b * N_EXP + e] = acc[e] * inv;
    }
}

// ---------------------------------------------------------------------------
// fp16 mma.sync GEMM, single term, BK=64, 3 stages, 4 warps, warp tile 64x64.
// mode 1: Oh = fp16(gelu(D+bias));  mode 0: Oh = fp16(D+bias)
// ---------------------------------------------------------------------------
#define TILE_B   16384                   // 128 x 64 fp16
#define STAGE_B  (2 * TILE_B)            // A, B
#define STAGES   3
#define SMEM_BYTES (STAGES * STAGE_B)    // 96 KB
#define CHUNKS   (DIMK / 64)             // 16

__device__ __forceinline__ void load_chunk(uint32_t stage_base,
                                           const __half* pA,
                                           const __half* pB,
                                           int k0, int tid) {
#pragma unroll
    for (int i = 0; i < 8; i++) {
        int id = tid + i * 128;          // 0..1023
        int r = id >> 3;                 // 0..127
        int c = id & 7;                  // 16B chunk 0..7
        uint32_t o = swz(r, c);
        const size_t s = (size_t)r * DIMK + k0 + c * 8;
        cp16(stage_base + o,          pA + s);
        cp16(stage_base + TILE_B + o, pB + s);
    }
}

__global__ void __launch_bounds__(128, 2) gemm_mma_kernel(
    const __half* __restrict__ A, size_t a_estride,
    const __half* __restrict__ Bw,
    const float* __restrict__ bias, int mode,
    __half* __restrict__ Oh)
{
    extern __shared__ char smem[];
    const int tid  = threadIdx.x;
    const int wid  = tid >> 5;
    const int lane = tid & 31;
    const int cb = blockIdx.x;
    const int rb = blockIdx.y;
    const int e  = blockIdx.z;
    const int wm = (wid >> 1) * 64;
    const int wn = (wid & 1) * 64;

    const uint32_t sbase = (uint32_t)__cvta_generic_to_shared(smem);

    const __half* pA = A + (size_t)e * a_estride + (size_t)rb * 128 * DIMK;
    const __half* pB = Bw + ((size_t)e * DIMK + (size_t)cb * 128) * DIMK;

    float acc[4][8][4];
#pragma unroll
    for (int i = 0; i < 4; i++)
#pragma unroll
        for (int j = 0; j < 8; j++)
#pragma unroll
            for (int k = 0; k < 4; k++) acc[i][j][k] = 0.f;

#pragma unroll
    for (int s = 0; s < STAGES - 1; s++) {
        load_chunk(sbase + s * STAGE_B, pA, pB, s * 64, tid);
        asm volatile("cp.async.commit_group;" ::: "memory");
    }

    const int jA = lane >> 3;
    const int rA_base = ((jA & 1) << 3) + (lane & 7);
    const int cA_base = jA >> 1;
    const int jB = lane >> 3;
    const int rB_base = ((jB >> 1) << 3) + (lane & 7);
    const int cB_base = jB & 1;

    for (int c = 0; c < CHUNKS; c++) {
        const int pf = c + STAGES - 1;
        if (pf < CHUNKS) {
            asm volatile("cp.async.wait_group %0;" :: "n"(STAGES - 2) : "memory");
        } else {
            asm volatile("cp.async.wait_group 0;" ::: "memory");
        }
        __syncthreads();
        if (pf < CHUNKS) {
            load_chunk(sbase + (pf % STAGES) * STAGE_B, pA, pB, pf * 64, tid);
            asm volatile("cp.async.commit_group;" ::: "memory");
        }

        const uint32_t a_b = sbase + (c % STAGES) * STAGE_B;
        const uint32_t b_b = a_b + TILE_B;

#pragma unroll
        for (int ks = 0; ks < 4; ks++) {           // 4 k16-groups per 64-chunk
            const int kc0 = ks * 2;                // 16B-chunk index base
            uint32_t bw[8][2];
#pragma unroll
            for (int q = 0; q < 4; q++) {
                int rB = wn + q * 16 + rB_base;
                int cB = kc0 + cB_base;
                uint32_t o = swz(rB, cB);
                uint32_t t[4];
                ldsm_x4(t, b_b + o);
                bw[2 * q][0] = t[0]; bw[2 * q][1] = t[1];
                bw[2 * q + 1][0] = t[2]; bw[2 * q + 1][1] = t[3];
            }
#pragma unroll
            for (int mf = 0; mf < 4; mf++) {
                int rA = wm + mf * 16 + rA_base;
                int cA = kc0 + cA_base;
                uint32_t o = swz(rA, cA);
                uint32_t av[4];
                ldsm_x4(av, a_b + o);
#pragma unroll
                for (int nf = 0; nf < 8; nf++)
                    mma_f16(acc[mf][nf], av, bw[nf]);
            }
        }
    }

    // --------------------------- epilogue ---------------------------
    const float* bias_e = bias + (size_t)e * DIMK;
#pragma unroll
    for (int mf = 0; mf < 4; mf++) {
#pragma unroll
        for (int nf = 0; nf < 8; nf++) {
#pragma unroll
            for (int h = 0; h < 2; h++) {
                int row = rb * 128 + wm + mf * 16 + (lane >> 2) + h * 8;
                int col = cb * 128 + wn + nf * 8 + ((lane & 3) << 1);
                float v0 = acc[mf][nf][2 * h]     + bias_e[col];
                float v1 = acc[mf][nf][2 * h + 1] + bias_e[col + 1];
                size_t o = (size_t)e * ((size_t)B_ROWS * DIMK)
                         + (size_t)row * DIMK + col;
                if (mode) {
                    v0 = 0.5f * v0 * (1.0f + erff(v0 * 0.70710678118654752f));
                    v1 = 0.5f * v1 * (1.0f + erff(v1 * 0.70710678118654752f));
                }
                __half2 ph;
                ph.x = __float2half_rn(v0);
                ph.y = __float2half_rn(v1);
                *(__half2*)(Oh + o) = ph;
            }
        }
    }
}

// ---------------------------------------------------------------------------
// LayerNorm + combine: warp-per-expert, fp16 Y input, shfl reductions.
// ---------------------------------------------------------------------------
__global__ void __launch_bounds__(256) ln_combine_kernel(
    const float* __restrict__ gamma, const float* __restrict__ beta,
    float* __restrict__ out)
{
    __shared__ float ybuf[N_EXP][DIMK];
    const int b = blockIdx.x;
    const int tid = threadIdx.x;
    const int e = tid >> 5;
    const int lane = tid & 31;

    const uint4* y4 = (const uint4*)(g_Yh + ((size_t)e * B_ROWS + b) * DIMK);
    float v[32];
    float s = 0.f;
#pragma unroll
    for (int j = 0; j < 4; j++) {
        uint4 raw = y4[j * 32 + lane];
        const uint32_t wds[4] = {raw.x, raw.y, raw.z, raw.w};
#pragma unroll
        for (int q = 0; q < 4; q++) {
            __half2 h2 = *(const __half2*)&wds[q];
            float2 f = __half22float2(h2);
            v[j * 8 + q * 2]     = f.x;
            v[j * 8 + q * 2 + 1] = f.y;
            s += f.x + f.y;
        }
    }
#pragma unroll
    for (int st = 16; st; st >>= 1) s += __shfl_xor_sync(0xffffffffu, s, st);
    const float mu = s * (1.f / DIMK);

    float s2 = 0.f;
#pragma unroll
    for (int i = 0; i < 32; i++) {
        float d = v[i] - mu;
        s2 += d * d;
    }
#pragma unroll
    for (int st = 16; st; st >>= 1) s2 += __shfl_xor_sync(0xffffffffu, s2, st);
    const float inv = rsqrtf(s2 * (1.f / DIMK) + 1e-5f);
    const float wgt = g_wts[(size_t)b * N_EXP + e];

    const float4* g4 = (const float4*)(gamma + (size_t)e * DIMK);
    const float4* b4 = (const float4*)(beta + (size_t)e * DIMK);
#pragma unroll
    for (int j = 0; j < 4; j++) {
        int base4 = (j * 32 + lane) * 2;
#pragma unroll
        for (int hh = 0; hh < 2; hh++) {
            float4 gg = g4[base4 + hh], bb = b4[base4 + hh], r;
            int vi = j * 8 + hh * 4;
            r.x = wgt * ((v[vi]     - mu) * inv * gg.x + bb.x);
            r.y = wgt * ((v[vi + 1] - mu) * inv * gg.y + bb.y);
            r.z = wgt * ((v[vi + 2] - mu) * inv * gg.z + bb.z);
            r.w = wgt * ((v[vi + 3] - mu) * inv * gg.w + bb.w);
            *(float4*)&ybuf[e][(base4 + hh) * 4] = r;
        }
    }
    __syncthreads();

    float4 a = *(float4*)&ybuf[0][tid * 4];
#pragma unroll
    for (int ee = 1; ee < N_EXP; ee++) {
        float4 u = *(float4*)&ybuf[ee][tid * 4];
        a.x += u.x; a.y += u.y; a.z += u.z; a.w += u.w;
    }
    *(float4*)(out + (size_t)b * DIMK + tid * 4) = a;
}

// ---------------------------------------------------------------------------
// Host launch
// ---------------------------------------------------------------------------
extern "C" void kernel_launch(void* const* d_in, const int* in_sizes, int n_in,
                              void* d_out, int out_size)
{
    const float* z_s   = (const float*)d_in[0];
    const float* z_e   = (const float*)d_in[1];
    const float* rw    = (const float*)d_in[2];
    const float* rb    = (const float*)d_in[3];
    const float* w1    = (const float*)d_in[4];
    const float* b1    = (const float*)d_in[5];
    const float* w2    = (const float*)d_in[6];
    const float* b2    = (const float*)d_in[7];
    const float* gamma = (const float*)d_in[8];
    const float* beta  = (const float*)d_in[9];
    float* out = (float*)d_out;

    __half *comb, *w1t, *w2t, *H, *Yh;
    cudaGetSymbolAddress((void**)&comb, g_comb);
    cudaGetSymbolAddress((void**)&w1t, g_w1t);
    cudaGetSymbolAddress((void**)&w2t, g_w2t);
    cudaGetSymbolAddress((void**)&H, g_H);
    cudaGetSymbolAddress((void**)&Yh, g_Yh);

    cudaFuncSetAttribute(gemm_mma_kernel,
                         cudaFuncAttributeMaxDynamicSharedMemorySize, SMEM_BYTES);

    {
        size_t total = (size_t)B_ROWS * DIMK;
        conv_comb_kernel<<<(int)((total + 255) / 256), 256>>>(z_s, z_e);
    }
    {
        dim3 tg(16, 16, 8);
        split_wT_kernel<<<tg, 256>>>(w1, w1t);
        split_wT_kernel<<<tg, 256>>>(w2, w2t);
    }
    router_kernel<<<B_ROWS / 8, 256>>>(z_s, z_e, rw, rb);

    dim3 grid(8, 128, 8);
    // GEMM1: H = fp16(gelu(comb @ w1 + b1))
    gemm_mma_kernel<<<grid, 128, SMEM_BYTES>>>(
        comb, (size_t)0, w1t, b1, 1, H);
    // GEMM2: Yh = fp16(H @ w2 + b2)
    gemm_mma_kernel<<<grid, 128, SMEM_BYTES>>>(
        H, (size_t)B_ROWS * DIMK, w2t, b2, 0, Yh);

    ln_combine_kernel<<<B_ROWS, 256>>>(gamma, beta, out);
}